// round 1
// baseline (speedup 1.0000x reference)
#include <cuda_runtime.h>
#include <cuda_bf16.h>

// ---------------- problem constants ----------------
#define LAYERS 4
#define NHEADS 4
#define H 64
#define DHD 16
#define FIN 32
#define ACT 15
#define OBSD 1500
#define HS 512
#define NOUTD 15
#define VHD 128
#define BATCH 128
#define NNODE 1000
#define TOTN (BATCH*NNODE)      // 128000
#define DEG 4
#define NEDGE (TOTN*DEG)        // 512000

// ---------------- scratch (static device globals; no allocation) ----------------
__device__ __align__(16) float g_x[TOTN*H];
__device__ __align__(16) float g_q[TOTN*H];
__device__ __align__(16) float g_k[TOTN*H];
__device__ __align__(16) float g_v[TOTN*H];
__device__ __align__(16) float g_agg[TOTN*H];
__device__ __align__(16) float g_hid[TOTN*2*H];
__device__ int g_deg[TOTN];
__device__ int g_rowptr[TOTN+1];
__device__ int g_cursor[TOTN];
__device__ int g_srcs[NEDGE];
__device__ float g_gat[BATCH*ACT];
__device__ __align__(16) float g_feat[BATCH*HS];
__device__ __align__(16) float g_feat2[BATCH*HS];
__device__ __align__(16) float g_vh[BATCH*VHD];
__device__ __align__(16) float g_vh2[BATCH*VHD];

typedef unsigned long long u64;

// ---------------- packed fp32x2 FMA helpers (Blackwell) ----------------
__device__ __forceinline__ u64 pk2(float a) {
    u64 r; asm("mov.b64 %0,{%1,%1};" : "=l"(r) : "f"(a)); return r;
}
__device__ __forceinline__ void ffma2(u64& d, u64 a, u64 b) {
    asm("fma.rn.f32x2 %0,%1,%2,%0;" : "+l"(d) : "l"(a), "l"(b));
}
__device__ __forceinline__ void unpk(u64 v, float& a, float& b) {
    asm("mov.b64 {%0,%1},%2;" : "=f"(a), "=f"(b) : "l"(v));
}

// row (KIN floats, in registers) x sW(KIN x STR, smem) -> 64 outputs accumulated
// into acc[32] packed pairs. sW may be pre-offset for output tiling.
template<int KIN, int STR>
__device__ __forceinline__ void mmrow(const float* xr, const float* sW, u64* acc) {
#pragma unroll 4
    for (int i = 0; i < KIN; i++) {
        u64 a = pk2(xr[i]);
        const u64* w = reinterpret_cast<const u64*>(sW + i * STR);
#pragma unroll
        for (int t = 0; t < 32; t++) ffma2(acc[t], a, w[t]);
    }
}

__device__ __forceinline__ void load_row(const float* p, float* xr, int nfloats) {
    const float4* fp = (const float4*)p;
#pragma unroll
    for (int i = 0; i < 32; i++) {
        if (i < nfloats / 4) {
            float4 f = fp[i];
            xr[4*i+0] = f.x; xr[4*i+1] = f.y; xr[4*i+2] = f.z; xr[4*i+3] = f.w;
        }
    }
}

__device__ __forceinline__ float dot4(float4 a, float4 b) {
    return a.x*b.x + a.y*b.y + a.z*b.z + a.w*b.w;
}

// ---------------- CSR build ----------------
__global__ void k_zero_deg() {
    int i = blockIdx.x * 256 + threadIdx.x;
    if (i < TOTN) g_deg[i] = 0;
}
__global__ void k_hist(const int* __restrict__ edst) {
    int e = blockIdx.x * 256 + threadIdx.x;
    if (e < NEDGE) atomicAdd(&g_deg[edst[e]], 1);
}
__global__ void k_scan() {  // <<<1,1024>>>, TOTN = 1024*125
    __shared__ int ssum[1024];
    int t = threadIdx.x;
    int base = t * 125;
    int s = 0;
    for (int i = 0; i < 125; i++) s += g_deg[base + i];
    ssum[t] = s;
    __syncthreads();
    if (t == 0) {
        int run = 0;
        for (int i = 0; i < 1024; i++) { int v = ssum[i]; ssum[i] = run; run += v; }
    }
    __syncthreads();
    int run = ssum[t];
    for (int i = 0; i < 125; i++) {
        g_rowptr[base + i] = run;
        g_cursor[base + i] = run;
        run += g_deg[base + i];
    }
    if (t == 1023) g_rowptr[TOTN] = run;
}
__global__ void k_scatter(const int* __restrict__ esrc, const int* __restrict__ edst) {
    int e = blockIdx.x * 256 + threadIdx.x;
    if (e < NEDGE) {
        int d = edst[e];
        int pos = atomicAdd(&g_cursor[d], 1);
        g_srcs[pos] = esrc[e];
    }
}

// ---------------- input projection: x = node_feats @ W_in ----------------
__global__ __launch_bounds__(128) void k_input(const float* __restrict__ nf,
                                               const float* __restrict__ Win) {
    __shared__ __align__(16) float sW[FIN*H];
    for (int i = threadIdx.x; i < FIN*H; i += 128) sW[i] = Win[i];
    __syncthreads();
    int node = blockIdx.x * 128 + threadIdx.x;
    float xr[FIN];
    load_row(nf + (size_t)node * FIN, xr, FIN);
    u64 acc[32];
#pragma unroll
    for (int t = 0; t < 32; t++) acc[t] = 0ull;
    mmrow<FIN, H>(xr, sW, acc);
    u64* o = (u64*)(g_x + (size_t)node * H);
#pragma unroll
    for (int t = 0; t < 32; t++) o[t] = acc[t];
}

// ---------------- q,k,v projections ----------------
__global__ __launch_bounds__(128) void k_qkv(const float* __restrict__ Wq,
                                             const float* __restrict__ Wk,
                                             const float* __restrict__ Wv) {
    __shared__ __align__(16) float sW[3*H*H];   // 48KB
    for (int i = threadIdx.x; i < H*H; i += 128) {
        sW[i] = Wq[i]; sW[H*H + i] = Wk[i]; sW[2*H*H + i] = Wv[i];
    }
    __syncthreads();
    int node = blockIdx.x * 128 + threadIdx.x;
    float xr[H];
    load_row(g_x + (size_t)node * H, xr, H);
    float* outs[3] = { g_q, g_k, g_v };
#pragma unroll
    for (int m = 0; m < 3; m++) {
        u64 acc[32];
#pragma unroll
        for (int t = 0; t < 32; t++) acc[t] = 0ull;
        mmrow<H, H>(xr, sW + m * H * H, acc);
        u64* o = (u64*)(outs[m] + (size_t)node * H);
#pragma unroll
        for (int t = 0; t < 32; t++) o[t] = acc[t];
    }
}

// ---------------- edge-softmax attention aggregate ----------------
__global__ void k_attn() {
    int t = blockIdx.x * 256 + threadIdx.x;
    if (t >= TOTN * NHEADS) return;
    int node = t >> 2, h = t & 3;
    const float4* qp = (const float4*)(g_q + (size_t)node * H + h * DHD);
    float4 q0 = qp[0], q1 = qp[1], q2 = qp[2], q3 = qp[3];
    int s0 = g_rowptr[node], s1 = g_rowptr[node + 1];
    float m = -1e30f;
    for (int e = s0; e < s1; e++) {
        int src = g_srcs[e];
        const float4* kp = (const float4*)(g_k + (size_t)src * H + h * DHD);
        float s = dot4(q0, kp[0]) + dot4(q1, kp[1]) + dot4(q2, kp[2]) + dot4(q3, kp[3]);
        m = fmaxf(m, s * 0.25f);
    }
    float den = 0.f;
    float a[DHD];
#pragma unroll
    for (int i = 0; i < DHD; i++) a[i] = 0.f;
    for (int e = s0; e < s1; e++) {
        int src = g_srcs[e];
        const float4* kp = (const float4*)(g_k + (size_t)src * H + h * DHD);
        float s = dot4(q0, kp[0]) + dot4(q1, kp[1]) + dot4(q2, kp[2]) + dot4(q3, kp[3]);
        float w = __expf(s * 0.25f - m);
        den += w;
        const float4* vp = (const float4*)(g_v + (size_t)src * H + h * DHD);
#pragma unroll
        for (int c = 0; c < 4; c++) {
            float4 vv = vp[c];
            a[4*c+0] += w * vv.x; a[4*c+1] += w * vv.y;
            a[4*c+2] += w * vv.z; a[4*c+3] += w * vv.w;
        }
    }
    float inv = 1.f / (den + 1e-9f);
    float4* op = (float4*)(g_agg + (size_t)node * H + h * DHD);
#pragma unroll
    for (int c = 0; c < 4; c++)
        op[c] = make_float4(a[4*c]*inv, a[4*c+1]*inv, a[4*c+2]*inv, a[4*c+3]*inv);
}

// ---------------- attn @ Wo + residual + LN ----------------
__global__ __launch_bounds__(128) void k_wo_ln(const float* __restrict__ Wo,
                                               const float* __restrict__ lg,
                                               const float* __restrict__ lb) {
    __shared__ __align__(16) float sW[H*H];
    __shared__ float sG[H], sB[H];
    for (int i = threadIdx.x; i < H*H; i += 128) sW[i] = Wo[i];
    if (threadIdx.x < H) { sG[threadIdx.x] = lg[threadIdx.x]; sB[threadIdx.x] = lb[threadIdx.x]; }
    __syncthreads();
    int node = blockIdx.x * 128 + threadIdx.x;
    float ar[H];
    load_row(g_agg + (size_t)node * H, ar, H);
    u64 acc[32];
#pragma unroll
    for (int t = 0; t < 32; t++) acc[t] = 0ull;
    mmrow<H, H>(ar, sW, acc);
    float o[H];
#pragma unroll
    for (int t = 0; t < 32; t++) unpk(acc[t], o[2*t], o[2*t+1]);
    const float4* xp = (const float4*)(g_x + (size_t)node * H);
    float mean = 0.f;
#pragma unroll
    for (int i = 0; i < 16; i++) {
        float4 f = xp[i];
        o[4*i+0] += f.x; o[4*i+1] += f.y; o[4*i+2] += f.z; o[4*i+3] += f.w;
    }
#pragma unroll
    for (int i = 0; i < H; i++) mean += o[i];
    mean *= (1.f / H);
    float var = 0.f;
#pragma unroll
    for (int i = 0; i < H; i++) { float d = o[i] - mean; var += d * d; }
    var *= (1.f / H);
    float r = rsqrtf(var + 1e-5f);
    float4* op = (float4*)(g_x + (size_t)node * H);
#pragma unroll
    for (int i = 0; i < 16; i++) {
        op[i] = make_float4((o[4*i+0]-mean)*r*sG[4*i+0]+sB[4*i+0],
                            (o[4*i+1]-mean)*r*sG[4*i+1]+sB[4*i+1],
                            (o[4*i+2]-mean)*r*sG[4*i+2]+sB[4*i+2],
                            (o[4*i+3]-mean)*r*sG[4*i+3]+sB[4*i+3]);
    }
}

// ---------------- FFN part 1: h = relu(x @ W1 + b1) ----------------
__global__ __launch_bounds__(128) void k_ffn1(const float* __restrict__ W1,
                                              const float* __restrict__ b1) {
    __shared__ __align__(16) float sW[H*2*H];   // 32KB
    __shared__ float sb[2*H];
    for (int i = threadIdx.x; i < H*2*H; i += 128) sW[i] = W1[i];
    if (threadIdx.x < 2*H) sb[threadIdx.x] = b1[threadIdx.x];
    __syncthreads();
    int node = blockIdx.x * 128 + threadIdx.x;
    float xr[H];
    load_row(g_x + (size_t)node * H, xr, H);
#pragma unroll
    for (int jh = 0; jh < 2; jh++) {
        u64 acc[32];
#pragma unroll
        for (int t = 0; t < 32; t++) acc[t] = 0ull;
        mmrow<H, 2*H>(xr, sW + jh * H, acc);
        float* o = g_hid + (size_t)node * 2 * H + jh * H;
#pragma unroll
        for (int t = 0; t < 32; t++) {
            float x0, x1; unpk(acc[t], x0, x1);
            x0 = fmaxf(x0 + sb[jh*H + 2*t],   0.f);
            x1 = fmaxf(x1 + sb[jh*H + 2*t+1], 0.f);
            *(float2*)(o + 2*t) = make_float2(x0, x1);
        }
    }
}

// ---------------- FFN part 2: x = LN(x + h @ W2 + b2) ----------------
__global__ __launch_bounds__(128) void k_ffn2(const float* __restrict__ W2,
                                              const float* __restrict__ b2,
                                              const float* __restrict__ lg,
                                              const float* __restrict__ lb) {
    __shared__ __align__(16) float sW[2*H*H];   // 32KB
    __shared__ float sb[H], sG[H], sB[H];
    for (int i = threadIdx.x; i < 2*H*H; i += 128) sW[i] = W2[i];
    if (threadIdx.x < H) {
        sb[threadIdx.x] = b2[threadIdx.x];
        sG[threadIdx.x] = lg[threadIdx.x];
        sB[threadIdx.x] = lb[threadIdx.x];
    }
    __syncthreads();
    int node = blockIdx.x * 128 + threadIdx.x;
    u64 acc[32];
#pragma unroll
    for (int t = 0; t < 32; t++) acc[t] = 0ull;
#pragma unroll
    for (int c = 0; c < 4; c++) {
        float hr[32];
        load_row(g_hid + (size_t)node * 2 * H + c * 32, hr, 32);
        mmrow<32, H>(hr, sW + (c * 32) * H, acc);
    }
    float o[H];
#pragma unroll
    for (int t = 0; t < 32; t++) unpk(acc[t], o[2*t], o[2*t+1]);
    const float4* xp = (const float4*)(g_x + (size_t)node * H);
#pragma unroll
    for (int i = 0; i < 16; i++) {
        float4 f = xp[i];
        o[4*i+0] += f.x + sb[4*i+0]; o[4*i+1] += f.y + sb[4*i+1];
        o[4*i+2] += f.z + sb[4*i+2]; o[4*i+3] += f.w + sb[4*i+3];
    }
    float mean = 0.f;
#pragma unroll
    for (int i = 0; i < H; i++) mean += o[i];
    mean *= (1.f / H);
    float var = 0.f;
#pragma unroll
    for (int i = 0; i < H; i++) { float d = o[i] - mean; var += d * d; }
    var *= (1.f / H);
    float r = rsqrtf(var + 1e-5f);
    float4* op = (float4*)(g_x + (size_t)node * H);
#pragma unroll
    for (int i = 0; i < 16; i++) {
        op[i] = make_float4((o[4*i+0]-mean)*r*sG[4*i+0]+sB[4*i+0],
                            (o[4*i+1]-mean)*r*sG[4*i+1]+sB[4*i+1],
                            (o[4*i+2]-mean)*r*sG[4*i+2]+sB[4*i+2],
                            (o[4*i+3]-mean)*r*sG[4*i+3]+sB[4*i+3]);
    }
}

// ---------------- readout: gat_out = x[agent] @ Wr + br ----------------
__global__ void k_gat(const int* __restrict__ an, const float* __restrict__ Wr,
                      const float* __restrict__ br) {
    __shared__ float sW[H*ACT];
    __shared__ float sb[ACT];
    int tid = threadIdx.x;
    for (int i = tid; i < H*ACT; i += 128) sW[i] = Wr[i];
    if (tid < ACT) sb[tid] = br[tid];
    __syncthreads();
    int b = tid;   // 128 threads
    int node = an[b];
    float acc[ACT];
#pragma unroll
    for (int j = 0; j < ACT; j++) acc[j] = sb[j];
    for (int i = 0; i < H; i++) {
        float xi = g_x[(size_t)node * H + i];
#pragma unroll
        for (int j = 0; j < ACT; j++) acc[j] += xi * sW[i*ACT + j];
    }
#pragma unroll
    for (int j = 0; j < ACT; j++) g_gat[b*ACT + j] = acc[j];
}

// ---------------- policy FC1: tanh(concat(gat,obs) @ Wp1 + bp1) ----------------
__global__ __launch_bounds__(512) void k_policy1(const float* __restrict__ obs,
                                                 const float* __restrict__ Wp1,
                                                 const float* __restrict__ bp1) {
    __shared__ float sr[ACT + OBSD];
    int b = blockIdx.x;
    for (int i = threadIdx.x; i < ACT; i += 512) sr[i] = g_gat[b*ACT + i];
    for (int i = threadIdx.x; i < OBSD; i += 512) sr[ACT + i] = obs[(size_t)b*OBSD + i];
    __syncthreads();
    int j = threadIdx.x;
    const float* W = Wp1 + j;
    float a0 = 0, a1 = 0, a2 = 0, a3 = 0;
    int i = 0;
    const int K = ACT + OBSD;   // 1515
    for (; i + 3 < K; i += 4) {
        a0 += sr[i+0] * W[(size_t)(i+0)*HS];
        a1 += sr[i+1] * W[(size_t)(i+1)*HS];
        a2 += sr[i+2] * W[(size_t)(i+2)*HS];
        a3 += sr[i+3] * W[(size_t)(i+3)*HS];
    }
    for (; i < K; i++) a0 += sr[i] * W[(size_t)i*HS];
    g_feat[b*HS + j] = tanhf(a0 + a1 + a2 + a3 + bp1[j]);
}

// ---------------- policy FC2: tanh(feat @ Wp2 + bp2) ----------------
__global__ __launch_bounds__(512) void k_policy2(const float* __restrict__ Wp2,
                                                 const float* __restrict__ bp2) {
    __shared__ float sr[HS];
    int b = blockIdx.x;
    for (int i = threadIdx.x; i < HS; i += 512) sr[i] = g_feat[b*HS + i];
    __syncthreads();
    int j = threadIdx.x;
    const float* W = Wp2 + j;
    float a0 = 0, a1 = 0, a2 = 0, a3 = 0;
    for (int i = 0; i < HS; i += 4) {
        a0 += sr[i+0] * W[(size_t)(i+0)*HS];
        a1 += sr[i+1] * W[(size_t)(i+1)*HS];
        a2 += sr[i+2] * W[(size_t)(i+2)*HS];
        a3 += sr[i+3] * W[(size_t)(i+3)*HS];
    }
    g_feat2[b*HS + j] = tanhf(a0 + a1 + a2 + a3 + bp2[j]);
}

// ---------------- logits = feat2 @ Wlog + blog -> d_out[0:1920] ----------------
__global__ void k_logits(const float* __restrict__ Wlog, const float* __restrict__ blog,
                         float* __restrict__ out) {
    int b = blockIdx.x;
    int j = threadIdx.x;
    if (j >= NOUTD) return;
    float acc = blog[j];
    for (int i = 0; i < HS; i++) acc += g_feat2[b*HS + i] * Wlog[i*NOUTD + j];
    out[b*NOUTD + j] = acc;
}

// ---------------- value branch ----------------
__global__ __launch_bounds__(VHD) void k_value1(const float* __restrict__ obs,
                                                const float* __restrict__ Wv1,
                                                const float* __restrict__ bv1) {
    __shared__ float sr[OBSD];
    int b = blockIdx.x;
    for (int i = threadIdx.x; i < OBSD; i += VHD) sr[i] = obs[(size_t)b*OBSD + i];
    __syncthreads();
    int j = threadIdx.x;
    const float* W = Wv1 + j;
    float a0 = 0, a1 = 0, a2 = 0, a3 = 0;
    for (int i = 0; i < OBSD; i += 4) {   // 1500 divisible by 4
        a0 += sr[i+0] * W[(size_t)(i+0)*VHD];
        a1 += sr[i+1] * W[(size_t)(i+1)*VHD];
        a2 += sr[i+2] * W[(size_t)(i+2)*VHD];
        a3 += sr[i+3] * W[(size_t)(i+3)*VHD];
    }
    g_vh[b*VHD + j] = tanhf(a0 + a1 + a2 + a3 + bv1[j]);
}

__global__ __launch_bounds__(VHD) void k_value2(const float* __restrict__ Wv2,
                                                const float* __restrict__ bv2) {
    __shared__ float sr[VHD];
    int b = blockIdx.x;
    sr[threadIdx.x] = g_vh[b*VHD + threadIdx.x];
    __syncthreads();
    int j = threadIdx.x;
    const float* W = Wv2 + j;
    float a0 = 0, a1 = 0, a2 = 0, a3 = 0;
    for (int i = 0; i < VHD; i += 4) {
        a0 += sr[i+0] * W[(i+0)*VHD];
        a1 += sr[i+1] * W[(i+1)*VHD];
        a2 += sr[i+2] * W[(i+2)*VHD];
        a3 += sr[i+3] * W[(i+3)*VHD];
    }
    g_vh2[b*VHD + j] = tanhf(a0 + a1 + a2 + a3 + bv2[j]);
}

__global__ void k_valueout(const float* __restrict__ Wvo, const float* __restrict__ bvo,
                           float* __restrict__ out) {
    int b = threadIdx.x;   // 128 threads
    float acc = bvo[0];
    for (int i = 0; i < VHD; i++) acc += g_vh2[b*VHD + i] * Wvo[i];
    out[BATCH*NOUTD + b] = acc;
}

// ---------------- launch ----------------
extern "C" void kernel_launch(void* const* d_in, const int* in_sizes, int n_in,
                              void* d_out, int out_size) {
    const float* node_feats = (const float*)d_in[0];
    const float* obs        = (const float*)d_in[1];
    const int*   edge_src   = (const int*)  d_in[2];
    const int*   edge_dst   = (const int*)  d_in[3];
    const int*   agent      = (const int*)  d_in[4];
    const float* W_in  = (const float*)d_in[5];
    const float* Wq    = (const float*)d_in[6];
    const float* Wk    = (const float*)d_in[7];
    const float* Wv    = (const float*)d_in[8];
    const float* Wo    = (const float*)d_in[9];
    const float* ln1g  = (const float*)d_in[10];
    const float* ln1b  = (const float*)d_in[11];
    const float* W1    = (const float*)d_in[12];
    const float* b1    = (const float*)d_in[13];
    const float* W2    = (const float*)d_in[14];
    const float* b2    = (const float*)d_in[15];
    const float* ln2g  = (const float*)d_in[16];
    const float* ln2b  = (const float*)d_in[17];
    const float* Wr    = (const float*)d_in[18];
    const float* br    = (const float*)d_in[19];
    const float* Wp1   = (const float*)d_in[20];
    const float* bp1   = (const float*)d_in[21];
    const float* Wp2   = (const float*)d_in[22];
    const float* bp2   = (const float*)d_in[23];
    const float* Wlog  = (const float*)d_in[24];
    const float* blog  = (const float*)d_in[25];
    const float* Wv1   = (const float*)d_in[26];
    const float* bv1   = (const float*)d_in[27];
    const float* Wv2   = (const float*)d_in[28];
    const float* bv2   = (const float*)d_in[29];
    const float* Wvo   = (const float*)d_in[30];
    const float* bvo   = (const float*)d_in[31];
    float* out = (float*)d_out;

    // CSR build (edges are inputs; rebuilt each launch, deterministic within fp tolerance)
    k_zero_deg<<<(TOTN + 255)/256, 256>>>();
    k_hist<<<(NEDGE + 255)/256, 256>>>(edge_dst);
    k_scan<<<1, 1024>>>();
    k_scatter<<<(NEDGE + 255)/256, 256>>>(edge_src, edge_dst);

    k_input<<<TOTN/128, 128>>>(node_feats, W_in);

    for (int l = 0; l < LAYERS; l++) {
        k_qkv  <<<TOTN/128, 128>>>(Wq + l*H*H, Wk + l*H*H, Wv + l*H*H);
        k_attn <<<(TOTN*NHEADS + 255)/256, 256>>>();
        k_wo_ln<<<TOTN/128, 128>>>(Wo + l*H*H, ln1g + l*H, ln1b + l*H);
        k_ffn1 <<<TOTN/128, 128>>>(W1 + l*H*2*H, b1 + l*2*H);
        k_ffn2 <<<TOTN/128, 128>>>(W2 + l*2*H*H, b2 + l*H, ln2g + l*H, ln2b + l*H);
    }

    k_gat<<<1, 128>>>(agent, Wr, br);
    k_policy1<<<BATCH, 512>>>(obs, Wp1, bp1);
    k_policy2<<<BATCH, 512>>>(Wp2, bp2);
    k_logits<<<BATCH, 32>>>(Wlog, blog, out);
    k_value1<<<BATCH, VHD>>>(obs, Wv1, bv1);
    k_value2<<<BATCH, VHD>>>(Wv2, bv2);
    k_valueout<<<1, BATCH>>>(Wvo, bvo, out);
}

// round 2
// speedup vs baseline: 1.2812x; 1.2812x over previous
#include <cuda_runtime.h>
#include <cuda_bf16.h>

// ---------------- problem constants ----------------
#define LAYERS 4
#define NHEADS 4
#define H 64
#define DHD 16
#define FIN 32
#define ACT 15
#define OBSD 1500
#define HS 512
#define NOUTD 15
#define VHD 128
#define BATCH 128
#define NNODE 1000
#define TOTN (BATCH*NNODE)      // 128000
#define DEG 4
#define NEDGE (TOTN*DEG)        // 512000

#define BM 128                  // nodes per block (GEMM tile M)
#define BMP 132                 // padded smem stride (floats), 132*4 % 16 == 0, conflict-free reads
#define SMEMSZ ((64*BMP + 64*64) * 4)   // 50176 bytes

// ---------------- scratch (static device globals; no allocation) ----------------
__device__ __align__(16) float g_x[TOTN*H];
__device__ __align__(16) float g_q[TOTN*H];
__device__ __align__(16) float g_k[TOTN*H];
__device__ __align__(16) float g_v[TOTN*H];
__device__ __align__(16) float g_agg[TOTN*H];
__device__ __align__(16) float g_hid[TOTN*2*H];
__device__ int g_deg[TOTN];
__device__ int g_rowptr[TOTN+1];
__device__ int g_cursor[TOTN];
__device__ int g_srcs[NEDGE];
__device__ float g_gat[BATCH*ACT];
__device__ __align__(16) float g_feat[BATCH*HS];
__device__ __align__(16) float g_feat2[BATCH*HS];
__device__ __align__(16) float g_vh[BATCH*VHD];
__device__ __align__(16) float g_vh2[BATCH*VHD];

typedef unsigned long long u64;

// ---------------- packed fp32x2 FMA helpers (Blackwell) ----------------
__device__ __forceinline__ u64 pk2(float a) {
    u64 r; asm("mov.b64 %0,{%1,%1};" : "=l"(r) : "f"(a)); return r;
}
__device__ __forceinline__ void ffma2(u64& d, u64 a, u64 b) {
    asm("fma.rn.f32x2 %0,%1,%2,%0;" : "+l"(d) : "l"(a), "l"(b));
}
__device__ __forceinline__ void unpk(u64 v, float& a, float& b) {
    asm("mov.b64 {%0,%1},%2;" : "=f"(a), "=f"(b) : "l"(v));
}
__device__ __forceinline__ float dot4(float4 a, float4 b) {
    return a.x*b.x + a.y*b.y + a.z*b.z + a.w*b.w;
}

// ---------------- GEMM building blocks ----------------
// Load BM x KC tile from g (row stride rs) transposed into sXT[k][row] (stride BMP).
template<int KC>
__device__ __forceinline__ void load_xt(const float* __restrict__ g, int rs,
                                        float* sXT, int tid) {
    constexpr int C4 = KC / 4;
#pragma unroll
    for (int it = 0; it < C4; it++) {
        int i = it * 128 + tid;
        int row = i / C4;
        int c4 = (i % C4) << 2;
        float4 f = *(const float4*)(g + (size_t)row * rs + c4);
        sXT[(c4+0)*BMP + row] = f.x;
        sXT[(c4+1)*BMP + row] = f.y;
        sXT[(c4+2)*BMP + row] = f.z;
        sXT[(c4+3)*BMP + row] = f.w;
    }
}
// Load KK x 64 weight tile from g (row stride rs) into sW row-major [k][64].
template<int KK>
__device__ __forceinline__ void load_w(const float* __restrict__ g, int rs,
                                       float* sW, int tid) {
#pragma unroll
    for (int it = 0; it < KK/8; it++) {
        int i = it * 128 + tid;
        int row = i >> 4;
        int c4 = (i & 15) << 2;
        *(float4*)(sW + row*64 + c4) = *(const float4*)(g + (size_t)row * rs + c4);
    }
}
// Accumulate 8x8 tile: rows r0..r0+7 from sXT, cols c0..c0+7 from sW.
template<int KK>
__device__ __forceinline__ void gemm_acc(const float* sXT, const float* sW,
                                         int r0, int c0, u64* acc) {
    const float* xp = sXT + r0;
    const float* wp0 = sW + c0;
#pragma unroll 4
    for (int k = 0; k < KK; k++) {
        float4 a0 = *(const float4*)(xp + k*BMP);
        float4 a1 = *(const float4*)(xp + k*BMP + 4);
        const u64* wp = (const u64*)(wp0 + k*64);
        u64 b0 = wp[0], b1 = wp[1], b2 = wp[2], b3 = wp[3];
        float ar[8] = {a0.x,a0.y,a0.z,a0.w,a1.x,a1.y,a1.z,a1.w};
#pragma unroll
        for (int r = 0; r < 8; r++) {
            u64 av = pk2(ar[r]);
            ffma2(acc[r*4+0], av, b0);
            ffma2(acc[r*4+1], av, b1);
            ffma2(acc[r*4+2], av, b2);
            ffma2(acc[r*4+3], av, b3);
        }
    }
}
__device__ __forceinline__ void zero_acc(u64* acc) {
#pragma unroll
    for (int t = 0; t < 32; t++) acc[t] = 0ull;
}
__device__ __forceinline__ void store_tile(float* __restrict__ g, int rs,
                                           int r0, int c0, const u64* acc) {
#pragma unroll
    for (int r = 0; r < 8; r++) {
        float o[8];
        unpk(acc[r*4+0], o[0], o[1]);
        unpk(acc[r*4+1], o[2], o[3]);
        unpk(acc[r*4+2], o[4], o[5]);
        unpk(acc[r*4+3], o[6], o[7]);
        float* p = g + (size_t)(r0+r) * rs + c0;
        *(float4*)p     = make_float4(o[0],o[1],o[2],o[3]);
        *(float4*)(p+4) = make_float4(o[4],o[5],o[6],o[7]);
    }
}
// Stage 8x8 tile into sOut (stride 65, aliases sXT region).
__device__ __forceinline__ void stage_tile(float* sOut, int r0, int c0, const u64* acc) {
#pragma unroll
    for (int r = 0; r < 8; r++) {
        float o[8];
        unpk(acc[r*4+0], o[0], o[1]);
        unpk(acc[r*4+1], o[2], o[3]);
        unpk(acc[r*4+2], o[4], o[5]);
        unpk(acc[r*4+3], o[6], o[7]);
#pragma unroll
        for (int j = 0; j < 8; j++) sOut[(r0+r)*65 + c0 + j] = o[j];
    }
}
// Per-thread-row residual + (optional bias) + LayerNorm; writes g_x row.
__device__ __forceinline__ void ln_row(const float* sOut, int node, int row,
                                       const float* __restrict__ bias,
                                       const float* __restrict__ lg,
                                       const float* __restrict__ lb) {
    float o[H];
#pragma unroll
    for (int i = 0; i < H; i++) o[i] = sOut[row*65 + i];
    const float4* xp = (const float4*)(g_x + (size_t)node * H);
#pragma unroll
    for (int i = 0; i < 16; i++) {
        float4 f = xp[i];
        o[4*i+0] += f.x; o[4*i+1] += f.y; o[4*i+2] += f.z; o[4*i+3] += f.w;
    }
    if (bias) {
#pragma unroll
        for (int i = 0; i < H; i++) o[i] += __ldg(&bias[i]);
    }
    float mean = 0.f;
#pragma unroll
    for (int i = 0; i < H; i++) mean += o[i];
    mean *= (1.f / H);
    float var = 0.f;
#pragma unroll
    for (int i = 0; i < H; i++) { float d = o[i] - mean; var += d * d; }
    var *= (1.f / H);
    float r = rsqrtf(var + 1e-5f);
    float4* op = (float4*)(g_x + (size_t)node * H);
#pragma unroll
    for (int i = 0; i < 16; i++) {
        op[i] = make_float4(
            (o[4*i+0]-mean)*r*__ldg(&lg[4*i+0]) + __ldg(&lb[4*i+0]),
            (o[4*i+1]-mean)*r*__ldg(&lg[4*i+1]) + __ldg(&lb[4*i+1]),
            (o[4*i+2]-mean)*r*__ldg(&lg[4*i+2]) + __ldg(&lb[4*i+2]),
            (o[4*i+3]-mean)*r*__ldg(&lg[4*i+3]) + __ldg(&lb[4*i+3]));
    }
}

// ---------------- CSR build ----------------
__global__ void k_zero_deg() {
    int i = blockIdx.x * 256 + threadIdx.x;
    if (i < TOTN) g_deg[i] = 0;
}
__global__ void k_hist(const int* __restrict__ edst) {
    int e = blockIdx.x * 256 + threadIdx.x;
    if (e < NEDGE) atomicAdd(&g_deg[edst[e]], 1);
}
__global__ void k_scan() {  // <<<1,1024>>>, TOTN = 1024*125
    __shared__ int ssum[1024];
    int t = threadIdx.x;
    int base = t * 125;
    int s = 0;
    for (int i = 0; i < 125; i++) s += g_deg[base + i];
    ssum[t] = s;
    __syncthreads();
    if (t == 0) {
        int run = 0;
        for (int i = 0; i < 1024; i++) { int v = ssum[i]; ssum[i] = run; run += v; }
    }
    __syncthreads();
    int run = ssum[t];
    for (int i = 0; i < 125; i++) {
        g_rowptr[base + i] = run;
        g_cursor[base + i] = run;
        run += g_deg[base + i];
    }
    if (t == 1023) g_rowptr[TOTN] = run;
}
__global__ void k_scatter(const int* __restrict__ esrc, const int* __restrict__ edst) {
    int e = blockIdx.x * 256 + threadIdx.x;
    if (e < NEDGE) {
        int d = edst[e];
        int pos = atomicAdd(&g_cursor[d], 1);
        g_srcs[pos] = esrc[e];
    }
}

// ---------------- input projection: x = node_feats @ W_in ----------------
__global__ __launch_bounds__(128, 4) void k_input(const float* __restrict__ nf,
                                                  const float* __restrict__ Win) {
    extern __shared__ float sm[];
    float* sXT = sm; float* sW = sm + 64*BMP;
    int tid = threadIdx.x;
    int node0 = blockIdx.x * BM;
    load_xt<FIN>(nf + (size_t)node0 * FIN, FIN, sXT, tid);
    load_w<FIN>(Win, 64, sW, tid);
    __syncthreads();
    int r0 = (tid >> 3) * 8, c0 = (tid & 7) * 8;
    u64 acc[32]; zero_acc(acc);
    gemm_acc<FIN>(sXT, sW, r0, c0, acc);
    store_tile(g_x + (size_t)node0 * H, H, r0, c0, acc);
}

// ---------------- q,k,v projections (3 passes sharing x-tile) ----------------
__global__ __launch_bounds__(128, 4) void k_qkv(const float* __restrict__ Wq,
                                                const float* __restrict__ Wk,
                                                const float* __restrict__ Wv) {
    extern __shared__ float sm[];
    float* sXT = sm; float* sW = sm + 64*BMP;
    int tid = threadIdx.x;
    int node0 = blockIdx.x * BM;
    load_xt<H>(g_x + (size_t)node0 * H, H, sXT, tid);
    int r0 = (tid >> 3) * 8, c0 = (tid & 7) * 8;
    const float* Ws[3] = { Wq, Wk, Wv };
    float* outs[3] = { g_q, g_k, g_v };
#pragma unroll
    for (int m = 0; m < 3; m++) {
        __syncthreads();                 // xT ready / prev-pass readers done
        load_w<H>(Ws[m], 64, sW, tid);
        __syncthreads();
        u64 acc[32]; zero_acc(acc);
        gemm_acc<H>(sXT, sW, r0, c0, acc);
        store_tile(outs[m] + (size_t)node0 * H, H, r0, c0, acc);
    }
}

// ---------------- edge-softmax attention aggregate ----------------
__global__ void k_attn() {
    int t = blockIdx.x * 256 + threadIdx.x;
    if (t >= TOTN * NHEADS) return;
    int node = t >> 2, h = t & 3;
    const float4* qp = (const float4*)(g_q + (size_t)node * H + h * DHD);
    float4 q0 = qp[0], q1 = qp[1], q2 = qp[2], q3 = qp[3];
    int s0 = g_rowptr[node], s1 = g_rowptr[node + 1];
    float m = -1e30f;
    for (int e = s0; e < s1; e++) {
        int src = g_srcs[e];
        const float4* kp = (const float4*)(g_k + (size_t)src * H + h * DHD);
        float s = dot4(q0, kp[0]) + dot4(q1, kp[1]) + dot4(q2, kp[2]) + dot4(q3, kp[3]);
        m = fmaxf(m, s * 0.25f);
    }
    float den = 0.f;
    float a[DHD];
#pragma unroll
    for (int i = 0; i < DHD; i++) a[i] = 0.f;
    for (int e = s0; e < s1; e++) {
        int src = g_srcs[e];
        const float4* kp = (const float4*)(g_k + (size_t)src * H + h * DHD);
        float s = dot4(q0, kp[0]) + dot4(q1, kp[1]) + dot4(q2, kp[2]) + dot4(q3, kp[3]);
        float w = __expf(s * 0.25f - m);
        den += w;
        const float4* vp = (const float4*)(g_v + (size_t)src * H + h * DHD);
#pragma unroll
        for (int c = 0; c < 4; c++) {
            float4 vv = vp[c];
            a[4*c+0] += w * vv.x; a[4*c+1] += w * vv.y;
            a[4*c+2] += w * vv.z; a[4*c+3] += w * vv.w;
        }
    }
    float inv = 1.f / (den + 1e-9f);
    float4* op = (float4*)(g_agg + (size_t)node * H + h * DHD);
#pragma unroll
    for (int c = 0; c < 4; c++)
        op[c] = make_float4(a[4*c]*inv, a[4*c+1]*inv, a[4*c+2]*inv, a[4*c+3]*inv);
}

// ---------------- agg @ Wo + residual + LN (fused) ----------------
__global__ __launch_bounds__(128, 4) void k_wo_ln(const float* __restrict__ Wo,
                                                  const float* __restrict__ lg,
                                                  const float* __restrict__ lb) {
    extern __shared__ float sm[];
    float* sXT = sm; float* sW = sm + 64*BMP;
    int tid = threadIdx.x;
    int node0 = blockIdx.x * BM;
    load_xt<H>(g_agg + (size_t)node0 * H, H, sXT, tid);
    load_w<H>(Wo, 64, sW, tid);
    __syncthreads();
    int r0 = (tid >> 3) * 8, c0 = (tid & 7) * 8;
    u64 acc[32]; zero_acc(acc);
    gemm_acc<H>(sXT, sW, r0, c0, acc);
    __syncthreads();                     // done reading sXT
    float* sOut = sXT;                   // reuse, stride 65
    stage_tile(sOut, r0, c0, acc);
    __syncthreads();
    ln_row(sOut, node0 + tid, tid, nullptr, lg, lb);
}

// ---------------- FFN part 1: h = relu(x @ W1 + b1), two N-halves ----------------
__global__ __launch_bounds__(128, 4) void k_ffn1(const float* __restrict__ W1,
                                                 const float* __restrict__ b1) {
    extern __shared__ float sm[];
    float* sXT = sm; float* sW = sm + 64*BMP;
    int tid = threadIdx.x;
    int node0 = blockIdx.x * BM;
    load_xt<H>(g_x + (size_t)node0 * H, H, sXT, tid);
    int r0 = (tid >> 3) * 8, c0 = (tid & 7) * 8;
#pragma unroll
    for (int pass = 0; pass < 2; pass++) {
        __syncthreads();
        load_w<H>(W1 + pass * 64, 2*H, sW, tid);   // cols pass*64.., row stride 128
        __syncthreads();
        u64 acc[32]; zero_acc(acc);
        gemm_acc<H>(sXT, sW, r0, c0, acc);
        // bias + relu + store
#pragma unroll
        for (int r = 0; r < 8; r++) {
            float o[8];
            unpk(acc[r*4+0], o[0], o[1]);
            unpk(acc[r*4+1], o[2], o[3]);
            unpk(acc[r*4+2], o[4], o[5]);
            unpk(acc[r*4+3], o[6], o[7]);
#pragma unroll
            for (int j = 0; j < 8; j++)
                o[j] = fmaxf(o[j] + __ldg(&b1[pass*64 + c0 + j]), 0.f);
            float* p = g_hid + (size_t)(node0 + r0 + r) * (2*H) + pass*64 + c0;
            *(float4*)p     = make_float4(o[0],o[1],o[2],o[3]);
            *(float4*)(p+4) = make_float4(o[4],o[5],o[6],o[7]);
        }
    }
}

// ---------------- FFN part 2: x = LN(x + h @ W2 + b2), two K-chunks ----------------
__global__ __launch_bounds__(128, 4) void k_ffn2(const float* __restrict__ W2,
                                                 const float* __restrict__ b2,
                                                 const float* __restrict__ lg,
                                                 const float* __restrict__ lb) {
    extern __shared__ float sm[];
    float* sXT = sm; float* sW = sm + 64*BMP;
    int tid = threadIdx.x;
    int node0 = blockIdx.x * BM;
    int r0 = (tid >> 3) * 8, c0 = (tid & 7) * 8;
    u64 acc[32]; zero_acc(acc);
#pragma unroll
    for (int ck = 0; ck < 2; ck++) {
        __syncthreads();                 // prev chunk readers done
        load_xt<H>(g_hid + (size_t)node0 * (2*H) + ck*64, 2*H, sXT, tid);
        load_w<H>(W2 + ck * 64 * 64, 64, sW, tid);
        __syncthreads();
        gemm_acc<H>(sXT, sW, r0, c0, acc);
    }
    __syncthreads();
    float* sOut = sXT;
    stage_tile(sOut, r0, c0, acc);
    __syncthreads();
    ln_row(sOut, node0 + tid, tid, b2, lg, lb);
}

// ---------------- readout: gat_out = x[agent] @ Wr + br ----------------
__global__ void k_gat(const int* __restrict__ an, const float* __restrict__ Wr,
                      const float* __restrict__ br) {
    __shared__ float sW[H*ACT];
    __shared__ float sb[ACT];
    int tid = threadIdx.x;
    for (int i = tid; i < H*ACT; i += 128) sW[i] = Wr[i];
    if (tid < ACT) sb[tid] = br[tid];
    __syncthreads();
    int b = tid;   // 128 threads
    int node = an[b];
    float acc[ACT];
#pragma unroll
    for (int j = 0; j < ACT; j++) acc[j] = sb[j];
    for (int i = 0; i < H; i++) {
        float xi = g_x[(size_t)node * H + i];
#pragma unroll
        for (int j = 0; j < ACT; j++) acc[j] += xi * sW[i*ACT + j];
    }
#pragma unroll
    for (int j = 0; j < ACT; j++) g_gat[b*ACT + j] = acc[j];
}

// ---------------- policy FC1 ----------------
__global__ __launch_bounds__(512) void k_policy1(const float* __restrict__ obs,
                                                 const float* __restrict__ Wp1,
                                                 const float* __restrict__ bp1) {
    __shared__ float sr[ACT + OBSD];
    int b = blockIdx.x;
    for (int i = threadIdx.x; i < ACT; i += 512) sr[i] = g_gat[b*ACT + i];
    for (int i = threadIdx.x; i < OBSD; i += 512) sr[ACT + i] = obs[(size_t)b*OBSD + i];
    __syncthreads();
    int j = threadIdx.x;
    const float* W = Wp1 + j;
    float a0 = 0, a1 = 0, a2 = 0, a3 = 0;
    int i = 0;
    const int K = ACT + OBSD;   // 1515
    for (; i + 3 < K; i += 4) {
        a0 += sr[i+0] * W[(size_t)(i+0)*HS];
        a1 += sr[i+1] * W[(size_t)(i+1)*HS];
        a2 += sr[i+2] * W[(size_t)(i+2)*HS];
        a3 += sr[i+3] * W[(size_t)(i+3)*HS];
    }
    for (; i < K; i++) a0 += sr[i] * W[(size_t)i*HS];
    g_feat[b*HS + j] = tanhf(a0 + a1 + a2 + a3 + bp1[j]);
}

// ---------------- policy FC2 ----------------
__global__ __launch_bounds__(512) void k_policy2(const float* __restrict__ Wp2,
                                                 const float* __restrict__ bp2) {
    __shared__ float sr[HS];
    int b = blockIdx.x;
    for (int i = threadIdx.x; i < HS; i += 512) sr[i] = g_feat[b*HS + i];
    __syncthreads();
    int j = threadIdx.x;
    const float* W = Wp2 + j;
    float a0 = 0, a1 = 0, a2 = 0, a3 = 0;
    for (int i = 0; i < HS; i += 4) {
        a0 += sr[i+0] * W[(size_t)(i+0)*HS];
        a1 += sr[i+1] * W[(size_t)(i+1)*HS];
        a2 += sr[i+2] * W[(size_t)(i+2)*HS];
        a3 += sr[i+3] * W[(size_t)(i+3)*HS];
    }
    g_feat2[b*HS + j] = tanhf(a0 + a1 + a2 + a3 + bp2[j]);
}

// ---------------- logits ----------------
__global__ void k_logits(const float* __restrict__ Wlog, const float* __restrict__ blog,
                         float* __restrict__ out) {
    int b = blockIdx.x;
    int j = threadIdx.x;
    if (j >= NOUTD) return;
    float acc = blog[j];
    for (int i = 0; i < HS; i++) acc += g_feat2[b*HS + i] * Wlog[i*NOUTD + j];
    out[b*NOUTD + j] = acc;
}

// ---------------- value branch ----------------
__global__ __launch_bounds__(VHD) void k_value1(const float* __restrict__ obs,
                                                const float* __restrict__ Wv1,
                                                const float* __restrict__ bv1) {
    __shared__ float sr[OBSD];
    int b = blockIdx.x;
    for (int i = threadIdx.x; i < OBSD; i += VHD) sr[i] = obs[(size_t)b*OBSD + i];
    __syncthreads();
    int j = threadIdx.x;
    const float* W = Wv1 + j;
    float a0 = 0, a1 = 0, a2 = 0, a3 = 0;
    for (int i = 0; i < OBSD; i += 4) {
        a0 += sr[i+0] * W[(size_t)(i+0)*VHD];
        a1 += sr[i+1] * W[(size_t)(i+1)*VHD];
        a2 += sr[i+2] * W[(size_t)(i+2)*VHD];
        a3 += sr[i+3] * W[(size_t)(i+3)*VHD];
    }
    g_vh[b*VHD + j] = tanhf(a0 + a1 + a2 + a3 + bv1[j]);
}

__global__ __launch_bounds__(VHD) void k_value2(const float* __restrict__ Wv2,
                                                const float* __restrict__ bv2) {
    __shared__ float sr[VHD];
    int b = blockIdx.x;
    sr[threadIdx.x] = g_vh[b*VHD + threadIdx.x];
    __syncthreads();
    int j = threadIdx.x;
    const float* W = Wv2 + j;
    float a0 = 0, a1 = 0, a2 = 0, a3 = 0;
    for (int i = 0; i < VHD; i += 4) {
        a0 += sr[i+0] * W[(i+0)*VHD];
        a1 += sr[i+1] * W[(i+1)*VHD];
        a2 += sr[i+2] * W[(i+2)*VHD];
        a3 += sr[i+3] * W[(i+3)*VHD];
    }
    g_vh2[b*VHD + j] = tanhf(a0 + a1 + a2 + a3 + bv2[j]);
}

__global__ void k_valueout(const float* __restrict__ Wvo, const float* __restrict__ bvo,
                           float* __restrict__ out) {
    int b = threadIdx.x;   // 128 threads
    float acc = bvo[0];
    for (int i = 0; i < VHD; i++) acc += g_vh2[b*VHD + i] * Wvo[i];
    out[BATCH*NOUTD + b] = acc;
}

// ---------------- launch ----------------
extern "C" void kernel_launch(void* const* d_in, const int* in_sizes, int n_in,
                              void* d_out, int out_size) {
    const float* node_feats = (const float*)d_in[0];
    const float* obs        = (const float*)d_in[1];
    const int*   edge_src   = (const int*)  d_in[2];
    const int*   edge_dst   = (const int*)  d_in[3];
    const int*   agent      = (const int*)  d_in[4];
    const float* W_in  = (const float*)d_in[5];
    const float* Wq    = (const float*)d_in[6];
    const float* Wk    = (const float*)d_in[7];
    const float* Wv    = (const float*)d_in[8];
    const float* Wo    = (const float*)d_in[9];
    const float* ln1g  = (const float*)d_in[10];
    const float* ln1b  = (const float*)d_in[11];
    const float* W1    = (const float*)d_in[12];
    const float* b1    = (const float*)d_in[13];
    const float* W2    = (const float*)d_in[14];
    const float* b2    = (const float*)d_in[15];
    const float* ln2g  = (const float*)d_in[16];
    const float* ln2b  = (const float*)d_in[17];
    const float* Wr    = (const float*)d_in[18];
    const float* br    = (const float*)d_in[19];
    const float* Wp1   = (const float*)d_in[20];
    const float* bp1   = (const float*)d_in[21];
    const float* Wp2   = (const float*)d_in[22];
    const float* bp2   = (const float*)d_in[23];
    const float* Wlog  = (const float*)d_in[24];
    const float* blog  = (const float*)d_in[25];
    const float* Wv1   = (const float*)d_in[26];
    const float* bv1   = (const float*)d_in[27];
    const float* Wv2   = (const float*)d_in[28];
    const float* bv2   = (const float*)d_in[29];
    const float* Wvo   = (const float*)d_in[30];
    const float* bvo   = (const float*)d_in[31];
    float* out = (float*)d_out;

    // opt-in to >48KB dynamic smem (idempotent; host-side, not a stream op)
    cudaFuncSetAttribute((const void*)k_input, cudaFuncAttributeMaxDynamicSharedMemorySize, SMEMSZ);
    cudaFuncSetAttribute((const void*)k_qkv,   cudaFuncAttributeMaxDynamicSharedMemorySize, SMEMSZ);
    cudaFuncSetAttribute((const void*)k_wo_ln, cudaFuncAttributeMaxDynamicSharedMemorySize, SMEMSZ);
    cudaFuncSetAttribute((const void*)k_ffn1,  cudaFuncAttributeMaxDynamicSharedMemorySize, SMEMSZ);
    cudaFuncSetAttribute((const void*)k_ffn2,  cudaFuncAttributeMaxDynamicSharedMemorySize, SMEMSZ);

    const int NB = TOTN / BM;   // 1000

    // CSR build
    k_zero_deg<<<(TOTN + 255)/256, 256>>>();
    k_hist<<<(NEDGE + 255)/256, 256>>>(edge_dst);
    k_scan<<<1, 1024>>>();
    k_scatter<<<(NEDGE + 255)/256, 256>>>(edge_src, edge_dst);

    k_input<<<NB, 128, SMEMSZ>>>(node_feats, W_in);

    for (int l = 0; l < LAYERS; l++) {
        k_qkv  <<<NB, 128, SMEMSZ>>>(Wq + l*H*H, Wk + l*H*H, Wv + l*H*H);
        k_attn <<<(TOTN*NHEADS + 255)/256, 256>>>();
        k_wo_ln<<<NB, 128, SMEMSZ>>>(Wo + l*H*H, ln1g + l*H, ln1b + l*H);
        k_ffn1 <<<NB, 128, SMEMSZ>>>(W1 + l*H*2*H, b1 + l*2*H);
        k_ffn2 <<<NB, 128, SMEMSZ>>>(W2 + l*2*H*H, b2 + l*H, ln2g + l*H, ln2b + l*H);
    }

    k_gat<<<1, 128>>>(agent, Wr, br);
    k_policy1<<<BATCH, 512>>>(obs, Wp1, bp1);
    k_policy2<<<BATCH, 512>>>(Wp2, bp2);
    k_logits<<<BATCH, 32>>>(Wlog, blog, out);
    k_value1<<<BATCH, VHD>>>(obs, Wv1, bv1);
    k_value2<<<BATCH, VHD>>>(Wv2, bv2);
    k_valueout<<<1, BATCH>>>(Wvo, bvo, out);
}

// round 4
// speedup vs baseline: 1.3213x; 1.0313x over previous
#include <cuda_runtime.h>
#include <cuda_bf16.h>

// ---------------- problem constants ----------------
#define LAYERS 4
#define NHEADS 4
#define H 64
#define DHD 16
#define FIN 32
#define ACT 15
#define OBSD 1500
#define HS 512
#define NOUTD 15
#define VHD 128
#define BATCH 128
#define NNODE 1000
#define TOTN (BATCH*NNODE)      // 128000
#define DEG 4
#define NEDGE (TOTN*DEG)        // 512000

#define BM 128                  // nodes per block (GEMM tile M)
#define BMP 132                 // padded smem stride (floats)
#define SMEMSZ ((64*BMP + 64*64) * 4)   // 50176 bytes

// ---------------- scratch (static device globals; no allocation) ----------------
__device__ __align__(16) float g_x[TOTN*H];
__device__ __align__(16) float g_q[TOTN*H];
__device__ __align__(16) float g_k[TOTN*H];
__device__ __align__(16) float g_v[TOTN*H];
__device__ __align__(16) float g_agg[TOTN*H];
__device__ __align__(16) float g_hid[TOTN*2*H];
__device__ int g_deg[TOTN];
__device__ int g_rowptr[TOTN+1];
__device__ int g_cursor[TOTN];
__device__ int g_srcs[NEDGE];
__device__ float g_gat[BATCH*ACT];
__device__ __align__(16) float g_feat[BATCH*HS];
__device__ __align__(16) float g_feat2[BATCH*HS];
__device__ __align__(16) float g_vh[BATCH*VHD];
__device__ __align__(16) float g_vh2[BATCH*VHD];

typedef unsigned long long u64;

// ---------------- packed fp32x2 FMA helpers (Blackwell) ----------------
__device__ __forceinline__ u64 pk2(float a) {
    u64 r; asm("mov.b64 %0,{%1,%1};" : "=l"(r) : "f"(a)); return r;
}
__device__ __forceinline__ void ffma2(u64& d, u64 a, u64 b) {
    asm("fma.rn.f32x2 %0,%1,%2,%0;" : "+l"(d) : "l"(a), "l"(b));
}
__device__ __forceinline__ void unpk(u64 v, float& a, float& b) {
    asm("mov.b64 {%0,%1},%2;" : "=f"(a), "=f"(b) : "l"(v));
}

// ---------------- GEMM building blocks ----------------
template<int KC>
__device__ __forceinline__ void load_xt(const float* __restrict__ g, int rs,
                                        float* sXT, int tid) {
    constexpr int C4 = KC / 4;
#pragma unroll
    for (int it = 0; it < C4; it++) {
        int i = it * 128 + tid;
        int row = i / C4;
        int c4 = (i % C4) << 2;
        float4 f = *(const float4*)(g + (size_t)row * rs + c4);
        sXT[(c4+0)*BMP + row] = f.x;
        sXT[(c4+1)*BMP + row] = f.y;
        sXT[(c4+2)*BMP + row] = f.z;
        sXT[(c4+3)*BMP + row] = f.w;
    }
}
template<int KK>
__device__ __forceinline__ void load_w(const float* __restrict__ g, int rs,
                                       float* sW, int tid) {
#pragma unroll
    for (int it = 0; it < KK/8; it++) {
        int i = it * 128 + tid;
        int row = i >> 4;
        int c4 = (i & 15) << 2;
        *(float4*)(sW + row*64 + c4) = *(const float4*)(g + (size_t)row * rs + c4);
    }
}
template<int KK>
__device__ __forceinline__ void gemm_acc(const float* sXT, const float* sW,
                                         int r0, int c0, u64* acc) {
    const float* xp = sXT + r0;
    const float* wp0 = sW + c0;
#pragma unroll 4
    for (int k = 0; k < KK; k++) {
        float4 a0 = *(const float4*)(xp + k*BMP);
        float4 a1 = *(const float4*)(xp + k*BMP + 4);
        const u64* wp = (const u64*)(wp0 + k*64);
        u64 b0 = wp[0], b1 = wp[1], b2 = wp[2], b3 = wp[3];
        float ar[8] = {a0.x,a0.y,a0.z,a0.w,a1.x,a1.y,a1.z,a1.w};
#pragma unroll
        for (int r = 0; r < 8; r++) {
            u64 av = pk2(ar[r]);
            ffma2(acc[r*4+0], av, b0);
            ffma2(acc[r*4+1], av, b1);
            ffma2(acc[r*4+2], av, b2);
            ffma2(acc[r*4+3], av, b3);
        }
    }
}
__device__ __forceinline__ void zero_acc(u64* acc) {
#pragma unroll
    for (int t = 0; t < 32; t++) acc[t] = 0ull;
}
__device__ __forceinline__ void store_tile(float* __restrict__ g, int rs,
                                           int r0, int c0, const u64* acc) {
#pragma unroll
    for (int r = 0; r < 8; r++) {
        float o[8];
        unpk(acc[r*4+0], o[0], o[1]);
        unpk(acc[r*4+1], o[2], o[3]);
        unpk(acc[r*4+2], o[4], o[5]);
        unpk(acc[r*4+3], o[6], o[7]);
        float* p = g + (size_t)(r0+r) * rs + c0;
        *(float4*)p     = make_float4(o[0],o[1],o[2],o[3]);
        *(float4*)(p+4) = make_float4(o[4],o[5],o[6],o[7]);
    }
}
__device__ __forceinline__ void stage_tile(float* sOut, int r0, int c0, const u64* acc) {
#pragma unroll
    for (int r = 0; r < 8; r++) {
        float o[8];
        unpk(acc[r*4+0], o[0], o[1]);
        unpk(acc[r*4+1], o[2], o[3]);
        unpk(acc[r*4+2], o[4], o[5]);
        unpk(acc[r*4+3], o[6], o[7]);
#pragma unroll
        for (int j = 0; j < 8; j++) sOut[(r0+r)*65 + c0 + j] = o[j];
    }
}
__device__ __forceinline__ void ln_row(const float* sOut, int node, int row,
                                       const float* __restrict__ bias,
                                       const float* __restrict__ lg,
                                       const float* __restrict__ lb) {
    float o[H];
#pragma unroll
    for (int i = 0; i < H; i++) o[i] = sOut[row*65 + i];
    const float4* xp = (const float4*)(g_x + (size_t)node * H);
#pragma unroll
    for (int i = 0; i < 16; i++) {
        float4 f = xp[i];
        o[4*i+0] += f.x; o[4*i+1] += f.y; o[4*i+2] += f.z; o[4*i+3] += f.w;
    }
    if (bias) {
#pragma unroll
        for (int i = 0; i < H; i++) o[i] += __ldg(&bias[i]);
    }
    float mean = 0.f;
#pragma unroll
    for (int i = 0; i < H; i++) mean += o[i];
    mean *= (1.f / H);
    float var = 0.f;
#pragma unroll
    for (int i = 0; i < H; i++) { float d = o[i] - mean; var += d * d; }
    var *= (1.f / H);
    float r = rsqrtf(var + 1e-5f);
    float4* op = (float4*)(g_x + (size_t)node * H);
#pragma unroll
    for (int i = 0; i < 16; i++) {
        op[i] = make_float4(
            (o[4*i+0]-mean)*r*__ldg(&lg[4*i+0]) + __ldg(&lb[4*i+0]),
            (o[4*i+1]-mean)*r*__ldg(&lg[4*i+1]) + __ldg(&lb[4*i+1]),
            (o[4*i+2]-mean)*r*__ldg(&lg[4*i+2]) + __ldg(&lb[4*i+2]),
            (o[4*i+3]-mean)*r*__ldg(&lg[4*i+3]) + __ldg(&lb[4*i+3]));
    }
}

// ---------------- CSR build ----------------
__global__ void k_zero_deg() {
    int i = blockIdx.x * 256 + threadIdx.x;
    if (i < TOTN) g_deg[i] = 0;
}
__global__ void k_hist(const int* __restrict__ edst) {
    int e = blockIdx.x * 256 + threadIdx.x;
    if (e < NEDGE) atomicAdd(&g_deg[edst[e]], 1);
}
__global__ void k_scan() {
    __shared__ int ssum[1024];
    int t = threadIdx.x;
    int base = t * 125;
    int s = 0;
    for (int i = 0; i < 125; i++) s += g_deg[base + i];
    ssum[t] = s;
    __syncthreads();
    if (t == 0) {
        int run = 0;
        for (int i = 0; i < 1024; i++) { int v = ssum[i]; ssum[i] = run; run += v; }
    }
    __syncthreads();
    int run = ssum[t];
    for (int i = 0; i < 125; i++) {
        g_rowptr[base + i] = run;
        g_cursor[base + i] = run;
        run += g_deg[base + i];
    }
    if (t == 1023) g_rowptr[TOTN] = run;
}
__global__ void k_scatter(const int* __restrict__ esrc, const int* __restrict__ edst) {
    int e = blockIdx.x * 256 + threadIdx.x;
    if (e < NEDGE) {
        int d = edst[e];
        int pos = atomicAdd(&g_cursor[d], 1);
        g_srcs[pos] = esrc[e];
    }
}

// ---------------- input projection ----------------
__global__ __launch_bounds__(128, 4) void k_input(const float* __restrict__ nf,
                                                  const float* __restrict__ Win) {
    extern __shared__ float sm[];
    float* sXT = sm; float* sW = sm + 64*BMP;
    int tid = threadIdx.x;
    int node0 = blockIdx.x * BM;
    load_xt<FIN>(nf + (size_t)node0 * FIN, FIN, sXT, tid);
    load_w<FIN>(Win, 64, sW, tid);
    __syncthreads();
    int r0 = (tid >> 3) * 8, c0 = (tid & 7) * 8;
    u64 acc[32]; zero_acc(acc);
    gemm_acc<FIN>(sXT, sW, r0, c0, acc);
    store_tile(g_x + (size_t)node0 * H, H, r0, c0, acc);
}

// ---------------- q,k,v projections ----------------
__global__ __launch_bounds__(128, 4) void k_qkv(const float* __restrict__ Wq,
                                                const float* __restrict__ Wk,
                                                const float* __restrict__ Wv) {
    extern __shared__ float sm[];
    float* sXT = sm; float* sW = sm + 64*BMP;
    int tid = threadIdx.x;
    int node0 = blockIdx.x * BM;
    load_xt<H>(g_x + (size_t)node0 * H, H, sXT, tid);
    int r0 = (tid >> 3) * 8, c0 = (tid & 7) * 8;
    const float* Ws[3] = { Wq, Wk, Wv };
    float* outs[3] = { g_q, g_k, g_v };
#pragma unroll
    for (int m = 0; m < 3; m++) {
        __syncthreads();
        load_w<H>(Ws[m], 64, sW, tid);
        __syncthreads();
        u64 acc[32]; zero_acc(acc);
        gemm_acc<H>(sXT, sW, r0, c0, acc);
        store_tile(outs[m] + (size_t)node0 * H, H, r0, c0, acc);
    }
}

// ---------------- warp-per-node attention, online softmax, coalesced gathers ----
// lane l owns dims [2l, 2l+1]; head = l>>3 (8 lanes per head, 16 dims).
__global__ __launch_bounds__(256) void k_attn() {
    int warp = (blockIdx.x * 256 + threadIdx.x) >> 5;
    int lane = threadIdx.x & 31;
    if (warp >= TOTN) return;
    int node = warp;

    float2 q = *(const float2*)(g_q + (size_t)node * H + 2*lane);
    int s0 = g_rowptr[node], s1 = g_rowptr[node + 1];

    float m = -1e30f, den = 0.f;
    float ax = 0.f, ay = 0.f;

    for (int e = s0; e < s1; e++) {
        int src = g_srcs[e];                       // uniform across warp
        const float2* kr = (const float2*)(g_k + (size_t)src * H);
        const float2* vr = (const float2*)(g_v + (size_t)src * H);
        float2 kk = kr[lane];                      // coalesced 256B row
        float2 vv = vr[lane];
        float p = q.x * kk.x + q.y * kk.y;
        // reduce within 8-lane head group
        p += __shfl_xor_sync(0xffffffffu, p, 1);
        p += __shfl_xor_sync(0xffffffffu, p, 2);
        p += __shfl_xor_sync(0xffffffffu, p, 4);
        float s = p * 0.25f;                       // 1/sqrt(16)
        float mn = fmaxf(m, s);
        float scale = __expf(m - mn);              // exp(-inf-ish) -> 0 first iter
        float w = __expf(s - mn);
        den = den * scale + w;
        ax = ax * scale + w * vv.x;
        ay = ay * scale + w * vv.y;
        m = mn;
    }
    float inv = 1.f / (den + 1e-9f);
    *(float2*)(g_agg + (size_t)node * H + 2*lane) = make_float2(ax * inv, ay * inv);
}

// ---------------- agg @ Wo + residual + LN (fused) ----------------
__global__ __launch_bounds__(128, 4) void k_wo_ln(const float* __restrict__ Wo,
                                                  const float* __restrict__ lg,
                                                  const float* __restrict__ lb) {
    extern __shared__ float sm[];
    float* sXT = sm; float* sW = sm + 64*BMP;
    int tid = threadIdx.x;
    int node0 = blockIdx.x * BM;
    load_xt<H>(g_agg + (size_t)node0 * H, H, sXT, tid);
    load_w<H>(Wo, 64, sW, tid);
    __syncthreads();
    int r0 = (tid >> 3) * 8, c0 = (tid & 7) * 8;
    u64 acc[32]; zero_acc(acc);
    gemm_acc<H>(sXT, sW, r0, c0, acc);
    __syncthreads();
    float* sOut = sXT;
    stage_tile(sOut, r0, c0, acc);
    __syncthreads();
    ln_row(sOut, node0 + tid, tid, nullptr, lg, lb);
}

// ---------------- FFN part 1 ----------------
__global__ __launch_bounds__(128, 4) void k_ffn1(const float* __restrict__ W1,
                                                 const float* __restrict__ b1) {
    extern __shared__ float sm[];
    float* sXT = sm; float* sW = sm + 64*BMP;
    int tid = threadIdx.x;
    int node0 = blockIdx.x * BM;
    load_xt<H>(g_x + (size_t)node0 * H, H, sXT, tid);
    int r0 = (tid >> 3) * 8, c0 = (tid & 7) * 8;
#pragma unroll
    for (int pass = 0; pass < 2; pass++) {
        __syncthreads();
        load_w<H>(W1 + pass * 64, 2*H, sW, tid);
        __syncthreads();
        u64 acc[32]; zero_acc(acc);
        gemm_acc<H>(sXT, sW, r0, c0, acc);
#pragma unroll
        for (int r = 0; r < 8; r++) {
            float o[8];
            unpk(acc[r*4+0], o[0], o[1]);
            unpk(acc[r*4+1], o[2], o[3]);
            unpk(acc[r*4+2], o[4], o[5]);
            unpk(acc[r*4+3], o[6], o[7]);
#pragma unroll
            for (int j = 0; j < 8; j++)
                o[j] = fmaxf(o[j] + __ldg(&b1[pass*64 + c0 + j]), 0.f);
            float* p = g_hid + (size_t)(node0 + r0 + r) * (2*H) + pass*64 + c0;
            *(float4*)p     = make_float4(o[0],o[1],o[2],o[3]);
            *(float4*)(p+4) = make_float4(o[4],o[5],o[6],o[7]);
        }
    }
}

// ---------------- FFN part 2 ----------------
__global__ __launch_bounds__(128, 4) void k_ffn2(const float* __restrict__ W2,
                                                 const float* __restrict__ b2,
                                                 const float* __restrict__ lg,
                                                 const float* __restrict__ lb) {
    extern __shared__ float sm[];
    float* sXT = sm; float* sW = sm + 64*BMP;
    int tid = threadIdx.x;
    int node0 = blockIdx.x * BM;
    int r0 = (tid >> 3) * 8, c0 = (tid & 7) * 8;
    u64 acc[32]; zero_acc(acc);
#pragma unroll
    for (int ck = 0; ck < 2; ck++) {
        __syncthreads();
        load_xt<H>(g_hid + (size_t)node0 * (2*H) + ck*64, 2*H, sXT, tid);
        load_w<H>(W2 + ck * 64 * 64, 64, sW, tid);
        __syncthreads();
        gemm_acc<H>(sXT, sW, r0, c0, acc);
    }
    __syncthreads();
    float* sOut = sXT;
    stage_tile(sOut, r0, c0, acc);
    __syncthreads();
    ln_row(sOut, node0 + tid, tid, b2, lg, lb);
}

// ---------------- readout + heads ----------------
__global__ void k_gat(const int* __restrict__ an, const float* __restrict__ Wr,
                      const float* __restrict__ br) {
    __shared__ float sW[H*ACT];
    __shared__ float sb[ACT];
    int tid = threadIdx.x;
    for (int i = tid; i < H*ACT; i += 128) sW[i] = Wr[i];
    if (tid < ACT) sb[tid] = br[tid];
    __syncthreads();
    int b = tid;
    int node = an[b];
    float acc[ACT];
#pragma unroll
    for (int j = 0; j < ACT; j++) acc[j] = sb[j];
    for (int i = 0; i < H; i++) {
        float xi = g_x[(size_t)node * H + i];
#pragma unroll
        for (int j = 0; j < ACT; j++) acc[j] += xi * sW[i*ACT + j];
    }
#pragma unroll
    for (int j = 0; j < ACT; j++) g_gat[b*ACT + j] = acc[j];
}

__global__ __launch_bounds__(512) void k_policy1(const float* __restrict__ obs,
                                                 const float* __restrict__ Wp1,
                                                 const float* __restrict__ bp1) {
    __shared__ float sr[ACT + OBSD];
    int b = blockIdx.x;
    for (int i = threadIdx.x; i < ACT; i += 512) sr[i] = g_gat[b*ACT + i];
    for (int i = threadIdx.x; i < OBSD; i += 512) sr[ACT + i] = obs[(size_t)b*OBSD + i];
    __syncthreads();
    int j = threadIdx.x;
    const float* W = Wp1 + j;
    float a0 = 0, a1 = 0, a2 = 0, a3 = 0;
    int i = 0;
    const int K = ACT + OBSD;
    for (; i + 3 < K; i += 4) {
        a0 += sr[i+0] * W[(size_t)(i+0)*HS];
        a1 += sr[i+1] * W[(size_t)(i+1)*HS];
        a2 += sr[i+2] * W[(size_t)(i+2)*HS];
        a3 += sr[i+3] * W[(size_t)(i+3)*HS];
    }
    for (; i < K; i++) a0 += sr[i] * W[(size_t)i*HS];
    g_feat[b*HS + j] = tanhf(a0 + a1 + a2 + a3 + bp1[j]);
}

__global__ __launch_bounds__(512) void k_policy2(const float* __restrict__ Wp2,
                                                 const float* __restrict__ bp2) {
    __shared__ float sr[HS];
    int b = blockIdx.x;
    for (int i = threadIdx.x; i < HS; i += 512) sr[i] = g_feat[b*HS + i];
    __syncthreads();
    int j = threadIdx.x;
    const float* W = Wp2 + j;
    float a0 = 0, a1 = 0, a2 = 0, a3 = 0;
    for (int i = 0; i < HS; i += 4) {
        a0 += sr[i+0] * W[(size_t)(i+0)*HS];
        a1 += sr[i+1] * W[(size_t)(i+1)*HS];
        a2 += sr[i+2] * W[(size_t)(i+2)*HS];
        a3 += sr[i+3] * W[(size_t)(i+3)*HS];
    }
    g_feat2[b*HS + j] = tanhf(a0 + a1 + a2 + a3 + bp2[j]);
}

__global__ void k_logits(const float* __restrict__ Wlog, const float* __restrict__ blog,
                         float* __restrict__ out) {
    int b = blockIdx.x;
    int j = threadIdx.x;
    if (j >= NOUTD) return;
    float acc = blog[j];
    for (int i = 0; i < HS; i++) acc += g_feat2[b*HS + i] * Wlog[i*NOUTD + j];
    out[b*NOUTD + j] = acc;
}

__global__ __launch_bounds__(VHD) void k_value1(const float* __restrict__ obs,
                                                const float* __restrict__ Wv1,
                                                const float* __restrict__ bv1) {
    __shared__ float sr[OBSD];
    int b = blockIdx.x;
    for (int i = threadIdx.x; i < OBSD; i += VHD) sr[i] = obs[(size_t)b*OBSD + i];
    __syncthreads();
    int j = threadIdx.x;
    const float* W = Wv1 + j;
    float a0 = 0, a1 = 0, a2 = 0, a3 = 0;
    for (int i = 0; i < OBSD; i += 4) {
        a0 += sr[i+0] * W[(size_t)(i+0)*VHD];
        a1 += sr[i+1] * W[(size_t)(i+1)*VHD];
        a2 += sr[i+2] * W[(size_t)(i+2)*VHD];
        a3 += sr[i+3] * W[(size_t)(i+3)*VHD];
    }
    g_vh[b*VHD + j] = tanhf(a0 + a1 + a2 + a3 + bv1[j]);
}

__global__ __launch_bounds__(VHD) void k_value2(const float* __restrict__ Wv2,
                                                const float* __restrict__ bv2) {
    __shared__ float sr[VHD];
    int b = blockIdx.x;
    sr[threadIdx.x] = g_vh[b*VHD + threadIdx.x];
    __syncthreads();
    int j = threadIdx.x;
    const float* W = Wv2 + j;
    float a0 = 0, a1 = 0, a2 = 0, a3 = 0;
    for (int i = 0; i < VHD; i += 4) {
        a0 += sr[i+0] * W[(i+0)*VHD];
        a1 += sr[i+1] * W[(i+1)*VHD];
        a2 += sr[i+2] * W[(i+2)*VHD];
        a3 += sr[i+3] * W[(i+3)*VHD];
    }
    g_vh2[b*VHD + j] = tanhf(a0 + a1 + a2 + a3 + bv2[j]);
}

__global__ void k_valueout(const float* __restrict__ Wvo, const float* __restrict__ bvo,
                           float* __restrict__ out) {
    int b = threadIdx.x;
    float acc = bvo[0];
    for (int i = 0; i < VHD; i++) acc += g_vh2[b*VHD + i] * Wvo[i];
    out[BATCH*NOUTD + b] = acc;
}

// ---------------- launch ----------------
extern "C" void kernel_launch(void* const* d_in, const int* in_sizes, int n_in,
                              void* d_out, int out_size) {
    const float* node_feats = (const float*)d_in[0];
    const float* obs        = (const float*)d_in[1];
    const int*   edge_src   = (const int*)  d_in[2];
    const int*   edge_dst   = (const int*)  d_in[3];
    const int*   agent      = (const int*)  d_in[4];
    const float* W_in  = (const float*)d_in[5];
    const float* Wq    = (const float*)d_in[6];
    const float* Wk    = (const float*)d_in[7];
    const float* Wv    = (const float*)d_in[8];
    const float* Wo    = (const float*)d_in[9];
    const float* ln1g  = (const float*)d_in[10];
    const float* ln1b  = (const float*)d_in[11];
    const float* W1    = (const float*)d_in[12];
    const float* b1    = (const float*)d_in[13];
    const float* W2    = (const float*)d_in[14];
    const float* b2    = (const float*)d_in[15];
    const float* ln2g  = (const float*)d_in[16];
    const float* ln2b  = (const float*)d_in[17];
    const float* Wr    = (const float*)d_in[18];
    const float* br    = (const float*)d_in[19];
    const float* Wp1   = (const float*)d_in[20];
    const float* bp1   = (const float*)d_in[21];
    const float* Wp2   = (const float*)d_in[22];
    const float* bp2   = (const float*)d_in[23];
    const float* Wlog  = (const float*)d_in[24];
    const float* blog  = (const float*)d_in[25];
    const float* Wv1   = (const float*)d_in[26];
    const float* bv1   = (const float*)d_in[27];
    const float* Wv2   = (const float*)d_in[28];
    const float* bv2   = (const float*)d_in[29];
    const float* Wvo   = (const float*)d_in[30];
    const float* bvo   = (const float*)d_in[31];
    float* out = (float*)d_out;

    cudaFuncSetAttribute((const void*)k_input, cudaFuncAttributeMaxDynamicSharedMemorySize, SMEMSZ);
    cudaFuncSetAttribute((const void*)k_qkv,   cudaFuncAttributeMaxDynamicSharedMemorySize, SMEMSZ);
    cudaFuncSetAttribute((const void*)k_wo_ln, cudaFuncAttributeMaxDynamicSharedMemorySize, SMEMSZ);
    cudaFuncSetAttribute((const void*)k_ffn1,  cudaFuncAttributeMaxDynamicSharedMemorySize, SMEMSZ);
    cudaFuncSetAttribute((const void*)k_ffn2,  cudaFuncAttributeMaxDynamicSharedMemorySize, SMEMSZ);

    const int NB = TOTN / BM;   // 1000

    k_zero_deg<<<(TOTN + 255)/256, 256>>>();
    k_hist<<<(NEDGE + 255)/256, 256>>>(edge_dst);
    k_scan<<<1, 1024>>>();
    k_scatter<<<(NEDGE + 255)/256, 256>>>(edge_src, edge_dst);

    k_input<<<NB, 128, SMEMSZ>>>(node_feats, W_in);

    for (int l = 0; l < LAYERS; l++) {
        k_qkv  <<<NB, 128, SMEMSZ>>>(Wq + l*H*H, Wk + l*H*H, Wv + l*H*H);
        k_attn <<<(TOTN*32 + 255)/256, 256>>>();           // warp per node
        k_wo_ln<<<NB, 128, SMEMSZ>>>(Wo + l*H*H, ln1g + l*H, ln1b + l*H);
        k_ffn1 <<<NB, 128, SMEMSZ>>>(W1 + l*H*2*H, b1 + l*2*H);
        k_ffn2 <<<NB, 128, SMEMSZ>>>(W2 + l*2*H*H, b2 + l*H, ln2g + l*H, ln2b + l*H);
    }

    k_gat<<<1, 128>>>(agent, Wr, br);
    k_policy1<<<BATCH, 512>>>(obs, Wp1, bp1);
    k_policy2<<<BATCH, 512>>>(Wp2, bp2);
    k_logits<<<BATCH, 32>>>(Wlog, blog, out);
    k_value1<<<BATCH, VHD>>>(obs, Wv1, bv1);
    k_value2<<<BATCH, VHD>>>(Wv2, bv2);
    k_valueout<<<1, BATCH>>>(Wvo, bvo, out);
}

// round 7
// speedup vs baseline: 1.4600x; 1.1050x over previous
#include <cuda_runtime.h>
#include <cuda_bf16.h>
#include <cstdint>

// ---------------- problem constants ----------------
#define LAYERS 4
#define NHEADS 4
#define H 64
#define DHD 16
#define FIN 32
#define ACT 15
#define OBSD 1500
#define HS 512
#define NOUTD 15
#define VHD 128
#define BATCH 128
#define NNODE 1000
#define TOTN (BATCH*NNODE)      // 128000
#define DEG 4
#define NEDGE (TOTN*DEG)        // 512000

#define BM 128                  // nodes per block
#define NB (TOTN/BM)            // 1000
#define NTHR 256                // 8 warps (HMMA kernels)

// fp32x2 SIMT GEMM config (R4-proven)
#define BMP 132
#define SMEMSZ ((64*BMP + 64*64) * 4)   // 50176

// HMMA smem strides (bf16 elems); row pad 16B mod 128B -> conflict-free ldmatrix
#define SA64 72
#define A64_B   (128*SA64*2)        // 18432
#define B64_B   (64*SA64*2)         // 9216
#define B128_B  (128*SA64*2)        // 18432
#define SM_IN    (2*A64_B + 2*B64_B)    // 55296
#define SM_QKV   (2*A64_B + 2*B64_B)    // 55296
#define SM_FFN1  (2*A64_B + 2*B128_B)   // 73728

// ---------------- scratch ----------------
__device__ __align__(16) float g_x[TOTN*H];
__device__ __align__(16) float g_q[TOTN*H];
__device__ __align__(16) float g_k[TOTN*H];
__device__ __align__(16) float g_v[TOTN*H];
__device__ __align__(16) float g_agg[TOTN*H];
__device__ __align__(16) float g_hid[TOTN*2*H];
__device__ int g_deg[TOTN];
__device__ int g_rowptr[TOTN+1];
__device__ int g_cursor[TOTN];
__device__ int g_srcs[NEDGE];
__device__ float g_gat[BATCH*ACT];
__device__ __align__(16) float g_feat[BATCH*HS];
__device__ __align__(16) float g_feat2[BATCH*HS];
__device__ __align__(16) float g_vh[BATCH*VHD];
__device__ __align__(16) float g_vh2[BATCH*VHD];

typedef unsigned long long u64;

// ---------------- fp32x2 helpers (SIMT GEMM path) ----------------
__device__ __forceinline__ u64 pk2(float a){
    u64 r; asm("mov.b64 %0,{%1,%1};" : "=l"(r) : "f"(a)); return r;
}
__device__ __forceinline__ void ffma2(u64& d, u64 a, u64 b){
    asm("fma.rn.f32x2 %0,%1,%2,%0;" : "+l"(d) : "l"(a), "l"(b));
}
__device__ __forceinline__ void unpk(u64 v, float& a, float& b){
    asm("mov.b64 {%0,%1},%2;" : "=f"(a), "=f"(b) : "l"(v));
}

template<int KC>
__device__ __forceinline__ void load_xt(const float* __restrict__ g, int rs,
                                        float* sXT, int tid){
    constexpr int C4 = KC / 4;
#pragma unroll
    for (int it = 0; it < C4; it++){
        int i = it * 128 + tid;
        int row = i / C4;
        int c4 = (i % C4) << 2;
        float4 f = *(const float4*)(g + (size_t)row * rs + c4);
        sXT[(c4+0)*BMP + row] = f.x;
        sXT[(c4+1)*BMP + row] = f.y;
        sXT[(c4+2)*BMP + row] = f.z;
        sXT[(c4+3)*BMP + row] = f.w;
    }
}
template<int KK>
__device__ __forceinline__ void load_w(const float* __restrict__ g, int rs,
                                       float* sW, int tid){
#pragma unroll
    for (int it = 0; it < KK/8; it++){
        int i = it * 128 + tid;
        int row = i >> 4;
        int c4 = (i & 15) << 2;
        *(float4*)(sW + row*64 + c4) = *(const float4*)(g + (size_t)row * rs + c4);
    }
}
template<int KK>
__device__ __forceinline__ void gemm_acc(const float* sXT, const float* sW,
                                         int r0, int c0, u64* acc){
    const float* xp = sXT + r0;
    const float* wp0 = sW + c0;
#pragma unroll 4
    for (int k = 0; k < KK; k++){
        float4 a0 = *(const float4*)(xp + k*BMP);
        float4 a1 = *(const float4*)(xp + k*BMP + 4);
        const u64* wp = (const u64*)(wp0 + k*64);
        u64 b0 = wp[0], b1 = wp[1], b2 = wp[2], b3 = wp[3];
        float ar[8] = {a0.x,a0.y,a0.z,a0.w,a1.x,a1.y,a1.z,a1.w};
#pragma unroll
        for (int r = 0; r < 8; r++){
            u64 av = pk2(ar[r]);
            ffma2(acc[r*4+0], av, b0);
            ffma2(acc[r*4+1], av, b1);
            ffma2(acc[r*4+2], av, b2);
            ffma2(acc[r*4+3], av, b3);
        }
    }
}
__device__ __forceinline__ void zero_uacc(u64* acc){
#pragma unroll
    for (int t = 0; t < 32; t++) acc[t] = 0ull;
}
__device__ __forceinline__ void stage_tile(float* sOut, int r0, int c0, const u64* acc){
#pragma unroll
    for (int r = 0; r < 8; r++){
        float o[8];
        unpk(acc[r*4+0], o[0], o[1]);
        unpk(acc[r*4+1], o[2], o[3]);
        unpk(acc[r*4+2], o[4], o[5]);
        unpk(acc[r*4+3], o[6], o[7]);
#pragma unroll
        for (int j = 0; j < 8; j++) sOut[(r0+r)*65 + c0 + j] = o[j];
    }
}
__device__ __forceinline__ void ln_row(const float* sOut, int node, int row,
                                       const float* __restrict__ bias,
                                       const float* __restrict__ lg,
                                       const float* __restrict__ lb){
    float o[H];
#pragma unroll
    for (int i = 0; i < H; i++) o[i] = sOut[row*65 + i];
    const float4* xp = (const float4*)(g_x + (size_t)node * H);
#pragma unroll
    for (int i = 0; i < 16; i++){
        float4 f = xp[i];
        o[4*i+0] += f.x; o[4*i+1] += f.y; o[4*i+2] += f.z; o[4*i+3] += f.w;
    }
    if (bias){
#pragma unroll
        for (int i = 0; i < H; i++) o[i] += __ldg(&bias[i]);
    }
    float mean = 0.f;
#pragma unroll
    for (int i = 0; i < H; i++) mean += o[i];
    mean *= (1.f / H);
    float var = 0.f;
#pragma unroll
    for (int i = 0; i < H; i++){ float d = o[i] - mean; var += d * d; }
    var *= (1.f / H);
    float r = rsqrtf(var + 1e-5f);
    float4* op = (float4*)(g_x + (size_t)node * H);
#pragma unroll
    for (int i = 0; i < 16; i++){
        op[i] = make_float4(
            (o[4*i+0]-mean)*r*__ldg(&lg[4*i+0]) + __ldg(&lb[4*i+0]),
            (o[4*i+1]-mean)*r*__ldg(&lg[4*i+1]) + __ldg(&lb[4*i+1]),
            (o[4*i+2]-mean)*r*__ldg(&lg[4*i+2]) + __ldg(&lb[4*i+2]),
            (o[4*i+3]-mean)*r*__ldg(&lg[4*i+3]) + __ldg(&lb[4*i+3]));
    }
}

// ---------------- HMMA helpers ----------------
__device__ __forceinline__ uint32_t smem_u32(const void* p){
    uint32_t a;
    asm("{ .reg .u64 t; cvta.to.shared.u64 t, %1; cvt.u32.u64 %0, t; }" : "=r"(a) : "l"(p));
    return a;
}
__device__ __forceinline__ void ldsm4(uint32_t* r, uint32_t addr){
    asm volatile("ldmatrix.sync.aligned.m8n8.x4.shared.b16 {%0,%1,%2,%3}, [%4];"
        : "=r"(r[0]),"=r"(r[1]),"=r"(r[2]),"=r"(r[3]) : "r"(addr));
}
__device__ __forceinline__ void mma4(float* c, const uint32_t* a, uint32_t b0, uint32_t b1){
    asm volatile("mma.sync.aligned.m16n8k16.row.col.f32.bf16.bf16.f32 "
        "{%0,%1,%2,%3}, {%4,%5,%6,%7}, {%8,%9}, {%0,%1,%2,%3};"
        : "+f"(c[0]),"+f"(c[1]),"+f"(c[2]),"+f"(c[3])
        : "r"(a[0]),"r"(a[1]),"r"(a[2]),"r"(a[3]), "r"(b0),"r"(b1));
}
__device__ __forceinline__ void pack2(float v0, float v1, uint32_t& hp, uint32_t& lp){
    __nv_bfloat16 h0 = __float2bfloat16(v0), h1 = __float2bfloat16(v1);
    float r0 = v0 - __bfloat162float(h0), r1 = v1 - __bfloat162float(h1);
    __nv_bfloat16 l0 = __float2bfloat16(r0), l1 = __float2bfloat16(r1);
    hp = ((uint32_t)__bfloat16_as_ushort(h1) << 16) | __bfloat16_as_ushort(h0);
    lp = ((uint32_t)__bfloat16_as_ushort(l1) << 16) | __bfloat16_as_ushort(l0);
}
template<int ROWS, int KC>
__device__ __forceinline__ void stage_Ah(const float* __restrict__ g, int rs,
                                         char* hi, char* lo, int tid){
    for (int idx = tid; idx < ROWS*(KC/8); idx += NTHR){
        int row = idx / (KC/8), c8 = (idx % (KC/8)) * 8;
        float4 f0 = *(const float4*)(g + (size_t)row*rs + c8);
        float4 f1 = *(const float4*)(g + (size_t)row*rs + c8 + 4);
        float v[8] = {f0.x,f0.y,f0.z,f0.w,f1.x,f1.y,f1.z,f1.w};
        uint32_t hp[4], lp[4];
#pragma unroll
        for (int j = 0; j < 4; j++) pack2(v[2*j], v[2*j+1], hp[j], lp[j]);
        *(uint4*)(hi + row*SA64*2 + c8*2) = make_uint4(hp[0],hp[1],hp[2],hp[3]);
        *(uint4*)(lo + row*SA64*2 + c8*2) = make_uint4(lp[0],lp[1],lp[2],lp[3]);
    }
}
template<int NN, int KC>
__device__ __forceinline__ void stage_Bh(const float* __restrict__ W, int ns,
                                         char* hi, char* lo, int tid){
    for (int idx = tid; idx < NN*(KC/8); idx += NTHR){
        int n = idx / (KC/8), k8 = (idx % (KC/8)) * 8;
        uint32_t hp[4], lp[4];
#pragma unroll
        for (int j = 0; j < 4; j++){
            float v0 = __ldg(W + (size_t)(k8+2*j)*ns + n);
            float v1 = __ldg(W + (size_t)(k8+2*j+1)*ns + n);
            pack2(v0, v1, hp[j], lp[j]);
        }
        *(uint4*)(hi + n*SA64*2 + k8*2) = make_uint4(hp[0],hp[1],hp[2],hp[3]);
        *(uint4*)(lo + n*SA64*2 + k8*2) = make_uint4(lp[0],lp[1],lp[2],lp[3]);
    }
}
template<int NT, int KS>
__device__ __forceinline__ void mma_loop(const char* A_hi, const char* A_lo,
                                         const char* B_hi, const char* B_lo,
                                         int lane, int m0, float acc[][4]){
    int q = lane >> 3, r = lane & 7;
    uint32_t aoff = (uint32_t)(m0 + ((q & 1) << 3) + r) * (SA64*2) + (((q >> 1) << 3) * 2);
    uint32_t ah = smem_u32(A_hi) + aoff, al = smem_u32(A_lo) + aoff;
    uint32_t boff = (uint32_t)(((q >> 1) << 3) + r) * (SA64*2) + (((q & 1) << 3) * 2);
    uint32_t bh0 = smem_u32(B_hi) + boff, bl0 = smem_u32(B_lo) + boff;
#pragma unroll
    for (int kk = 0; kk < KS; kk++){
        uint32_t af[4], alf[4];
        ldsm4(af,  ah + kk*32);
        ldsm4(alf, al + kk*32);
#pragma unroll
        for (int g2 = 0; g2 < NT/2; g2++){
            uint32_t bf[4], blf[4];
            ldsm4(bf,  bh0 + g2*16*(SA64*2) + kk*32);
            ldsm4(blf, bl0 + g2*16*(SA64*2) + kk*32);
            mma4(acc[g2*2],   af,  bf[0],  bf[1]);
            mma4(acc[g2*2+1], af,  bf[2],  bf[3]);
            mma4(acc[g2*2],   af,  blf[0], blf[1]);
            mma4(acc[g2*2+1], af,  blf[2], blf[3]);
            mma4(acc[g2*2],   alf, bf[0],  bf[1]);
            mma4(acc[g2*2+1], alf, bf[2],  bf[3]);
        }
    }
}
template<int NT>
__device__ __forceinline__ void zero_facc(float acc[][4]){
#pragma unroll
    for (int i = 0; i < NT; i++){ acc[i][0]=0; acc[i][1]=0; acc[i][2]=0; acc[i][3]=0; }
}
template<int NT, bool RELU>
__device__ __forceinline__ void store_frags(float* __restrict__ g, int rs, int m0,
                                            int lane, float acc[][4],
                                            const float* __restrict__ bias){
    int r = lane >> 2, c2 = (lane & 3) * 2;
#pragma unroll
    for (int nt = 0; nt < NT; nt++){
        int col = nt*8 + c2;
        float b0 = bias ? __ldg(bias+col) : 0.f;
        float b1 = bias ? __ldg(bias+col+1) : 0.f;
        float v0 = acc[nt][0]+b0, v1 = acc[nt][1]+b1;
        float v2 = acc[nt][2]+b0, v3 = acc[nt][3]+b1;
        if (RELU){ v0=fmaxf(v0,0.f); v1=fmaxf(v1,0.f); v2=fmaxf(v2,0.f); v3=fmaxf(v3,0.f); }
        *(float2*)(g + (size_t)(m0+r)*rs + col)   = make_float2(v0, v1);
        *(float2*)(g + (size_t)(m0+r+8)*rs + col) = make_float2(v2, v3);
    }
}

// ---------------- CSR build ----------------
__global__ void k_zero_deg(){
    int i = blockIdx.x * 256 + threadIdx.x;
    if (i < TOTN) g_deg[i] = 0;
}
__global__ void k_hist(const int* __restrict__ edst){
    int e = blockIdx.x * 256 + threadIdx.x;
    if (e < NEDGE) atomicAdd(&g_deg[edst[e]], 1);
}
__global__ void k_scan(){
    __shared__ int ssum[1024];
    int t = threadIdx.x;
    int base = t * 125;
    int s = 0;
    for (int i = 0; i < 125; i++) s += g_deg[base + i];
    ssum[t] = s;
    __syncthreads();
    if (t == 0){
        int run = 0;
        for (int i = 0; i < 1024; i++){ int v = ssum[i]; ssum[i] = run; run += v; }
    }
    __syncthreads();
    int run = ssum[t];
    for (int i = 0; i < 125; i++){
        g_rowptr[base + i] = run;
        g_cursor[base + i] = run;
        run += g_deg[base + i];
    }
    if (t == 1023) g_rowptr[TOTN] = run;
}
__global__ void k_scatter(const int* __restrict__ esrc, const int* __restrict__ edst){
    int e = blockIdx.x * 256 + threadIdx.x;
    if (e < NEDGE){
        int d = edst[e];
        int pos = atomicAdd(&g_cursor[d], 1);
        g_srcs[pos] = esrc[e];
    }
}

// ---------------- HMMA GEMM kernels ----------------
__global__ __launch_bounds__(NTHR) void k_input(const float* __restrict__ nf,
                                                const float* __restrict__ Win){
    extern __shared__ __align__(16) char sm[];
    char* A_hi = sm;              char* A_lo = A_hi + A64_B;
    char* B_hi = A_lo + A64_B;    char* B_lo = B_hi + B64_B;
    int tid = threadIdx.x, wid = tid >> 5, lane = tid & 31;
    int node0 = blockIdx.x * BM;
    stage_Ah<128, FIN>(nf + (size_t)node0 * FIN, FIN, A_hi, A_lo, tid);
    stage_Bh<64, FIN>(Win, 64, B_hi, B_lo, tid);
    __syncthreads();
    float acc[8][4]; zero_facc<8>(acc);
    mma_loop<8, 2>(A_hi, A_lo, B_hi, B_lo, lane, wid*16, acc);
    store_frags<8, false>(g_x + (size_t)node0 * H, H, wid*16, lane, acc, nullptr);
}

__global__ __launch_bounds__(NTHR) void k_qkv(const float* __restrict__ Wq,
                                              const float* __restrict__ Wk,
                                              const float* __restrict__ Wv){
    extern __shared__ __align__(16) char sm[];
    char* A_hi = sm;              char* A_lo = A_hi + A64_B;
    char* B_hi = A_lo + A64_B;    char* B_lo = B_hi + B64_B;
    int tid = threadIdx.x, wid = tid >> 5, lane = tid & 31;
    int node0 = blockIdx.x * BM;
    stage_Ah<128, H>(g_x + (size_t)node0 * H, H, A_hi, A_lo, tid);
    const float* Ws[3] = { Wq, Wk, Wv };
    float* outs[3] = { g_q, g_k, g_v };
#pragma unroll
    for (int m = 0; m < 3; m++){
        if (m > 0) __syncthreads();
        stage_Bh<64, H>(Ws[m], 64, B_hi, B_lo, tid);
        __syncthreads();
        float acc[8][4]; zero_facc<8>(acc);
        mma_loop<8, 4>(A_hi, A_lo, B_hi, B_lo, lane, wid*16, acc);
        store_frags<8, false>(outs[m] + (size_t)node0 * H, H, wid*16, lane, acc, nullptr);
    }
}

__global__ __launch_bounds__(NTHR) void k_ffn1(const float* __restrict__ W1,
                                               const float* __restrict__ b1){
    extern __shared__ __align__(16) char sm[];
    char* A_hi = sm;              char* A_lo = A_hi + A64_B;
    char* B_hi = A_lo + A64_B;    char* B_lo = B_hi + B128_B;
    int tid = threadIdx.x, wid = tid >> 5, lane = tid & 31;
    int node0 = blockIdx.x * BM;
    stage_Ah<128, H>(g_x + (size_t)node0 * H, H, A_hi, A_lo, tid);
    stage_Bh<128, H>(W1, 2*H, B_hi, B_lo, tid);
    __syncthreads();
    float acc[16][4]; zero_facc<16>(acc);
    mma_loop<16, 4>(A_hi, A_lo, B_hi, B_lo, lane, wid*16, acc);
    store_frags<16, true>(g_hid + (size_t)node0 * (2*H), 2*H, wid*16, lane, acc, b1);
}

// ---------------- SIMT fp32x2 GEMMs with fused LN (R4-proven) ----------------
__global__ __launch_bounds__(128, 4) void k_wo_ln(const float* __restrict__ Wo,
                                                  const float* __restrict__ lg,
                                                  const float* __restrict__ lb){
    extern __shared__ float smf[];
    float* sXT = smf; float* sW = smf + 64*BMP;
    int tid = threadIdx.x;
    int node0 = blockIdx.x * BM;
    load_xt<H>(g_agg + (size_t)node0 * H, H, sXT, tid);
    load_w<H>(Wo, 64, sW, tid);
    __syncthreads();
    int r0 = (tid >> 3) * 8, c0 = (tid & 7) * 8;
    u64 acc[32]; zero_uacc(acc);
    gemm_acc<H>(sXT, sW, r0, c0, acc);
    __syncthreads();
    float* sOut = sXT;
    stage_tile(sOut, r0, c0, acc);
    __syncthreads();
    ln_row(sOut, node0 + tid, tid, nullptr, lg, lb);
}

__global__ __launch_bounds__(128, 4) void k_ffn2(const float* __restrict__ W2,
                                                 const float* __restrict__ b2,
                                                 const float* __restrict__ lg,
                                                 const float* __restrict__ lb){
    extern __shared__ float smf[];
    float* sXT = smf; float* sW = smf + 64*BMP;
    int tid = threadIdx.x;
    int node0 = blockIdx.x * BM;
    int r0 = (tid >> 3) * 8, c0 = (tid & 7) * 8;
    u64 acc[32]; zero_uacc(acc);
#pragma unroll
    for (int ck = 0; ck < 2; ck++){
        __syncthreads();
        load_xt<H>(g_hid + (size_t)node0 * (2*H) + ck*64, 2*H, sXT, tid);
        load_w<H>(W2 + ck * 64 * 64, 64, sW, tid);
        __syncthreads();
        gemm_acc<H>(sXT, sW, r0, c0, acc);
    }
    __syncthreads();
    float* sOut = sXT;
    stage_tile(sOut, r0, c0, acc);
    __syncthreads();
    ln_row(sOut, node0 + tid, tid, b2, lg, lb);
}

// ---------------- warp-per-node attention (online softmax) ----------------
__global__ __launch_bounds__(256) void k_attn(){
    int warp = (blockIdx.x * 256 + threadIdx.x) >> 5;
    int lane = threadIdx.x & 31;
    if (warp >= TOTN) return;
    int node = warp;
    float2 q = *(const float2*)(g_q + (size_t)node * H + 2*lane);
    int s0 = g_rowptr[node], s1 = g_rowptr[node + 1];
    float m = -1e30f, den = 0.f, ax = 0.f, ay = 0.f;
    for (int e = s0; e < s1; e++){
        int src = g_srcs[e];
        float2 kk = *(const float2*)(g_k + (size_t)src * H + 2*lane);
        float2 vv = *(const float2*)(g_v + (size_t)src * H + 2*lane);
        float p = q.x * kk.x + q.y * kk.y;
        p += __shfl_xor_sync(0xffffffffu, p, 1);
        p += __shfl_xor_sync(0xffffffffu, p, 2);
        p += __shfl_xor_sync(0xffffffffu, p, 4);
        float s = p * 0.25f;
        float mn = fmaxf(m, s);
        float scale = __expf(m - mn);
        float w = __expf(s - mn);
        den = den * scale + w;
        ax = ax * scale + w * vv.x;
        ay = ay * scale + w * vv.y;
        m = mn;
    }
    float inv = 1.f / (den + 1e-9f);
    *(float2*)(g_agg + (size_t)node * H + 2*lane) = make_float2(ax * inv, ay * inv);
}

// ---------------- readout + heads ----------------
__global__ void k_gat(const int* __restrict__ an, const float* __restrict__ Wr,
                      const float* __restrict__ br){
    __shared__ float sW[H*ACT];
    __shared__ float sb[ACT];
    int tid = threadIdx.x;
    for (int i = tid; i < H*ACT; i += 128) sW[i] = Wr[i];
    if (tid < ACT) sb[tid] = br[tid];
    __syncthreads();
    int b = tid;
    int node = an[b];
    float acc[ACT];
#pragma unroll
    for (int j = 0; j < ACT; j++) acc[j] = sb[j];
    for (int i = 0; i < H; i++){
        float xi = g_x[(size_t)node * H + i];
#pragma unroll
        for (int j = 0; j < ACT; j++) acc[j] += xi * sW[i*ACT + j];
    }
#pragma unroll
    for (int j = 0; j < ACT; j++) g_gat[b*ACT + j] = acc[j];
}

__global__ __launch_bounds__(512) void k_policy1(const float* __restrict__ obs,
                                                 const float* __restrict__ Wp1,
                                                 const float* __restrict__ bp1){
    __shared__ float sr[ACT + OBSD];
    int b = blockIdx.x;
    for (int i = threadIdx.x; i < ACT; i += 512) sr[i] = g_gat[b*ACT + i];
    for (int i = threadIdx.x; i < OBSD; i += 512) sr[ACT + i] = obs[(size_t)b*OBSD + i];
    __syncthreads();
    int j = threadIdx.x;
    const float* W = Wp1 + j;
    float a0 = 0, a1 = 0, a2 = 0, a3 = 0;
    int i = 0;
    const int K = ACT + OBSD;
    for (; i + 3 < K; i += 4){
        a0 += sr[i+0] * W[(size_t)(i+0)*HS];
        a1 += sr[i+1] * W[(size_t)(i+1)*HS];
        a2 += sr[i+2] * W[(size_t)(i+2)*HS];
        a3 += sr[i+3] * W[(size_t)(i+3)*HS];
    }
    for (; i < K; i++) a0 += sr[i] * W[(size_t)i*HS];
    g_feat[b*HS + j] = tanhf(a0 + a1 + a2 + a3 + bp1[j]);
}

__global__ __launch_bounds__(512) void k_policy2(const float* __restrict__ Wp2,
                                                 const float* __restrict__ bp2){
    __shared__ float sr[HS];
    int b = blockIdx.x;
    for (int i = threadIdx.x; i < HS; i += 512) sr[i] = g_feat[b*HS + i];
    __syncthreads();
    int j = threadIdx.x;
    const float* W = Wp2 + j;
    float a0 = 0, a1 = 0, a2 = 0, a3 = 0;
    for (int i = 0; i < HS; i += 4){
        a0 += sr[i+0] * W[(size_t)(i+0)*HS];
        a1 += sr[i+1] * W[(size_t)(i+1)*HS];
        a2 += sr[i+2] * W[(size_t)(i+2)*HS];
        a3 += sr[i+3] * W[(size_t)(i+3)*HS];
    }
    g_feat2[b*HS + j] = tanhf(a0 + a1 + a2 + a3 + bp2[j]);
}

__global__ void k_logits(const float* __restrict__ Wlog, const float* __restrict__ blog,
                         float* __restrict__ out){
    int b = blockIdx.x;
    int j = threadIdx.x;
    if (j >= NOUTD) return;
    float acc = blog[j];
    for (int i = 0; i < HS; i++) acc += g_feat2[b*HS + i] * Wlog[i*NOUTD + j];
    out[b*NOUTD + j] = acc;
}

__global__ __launch_bounds__(VHD) void k_value1(const float* __restrict__ obs,
                                                const float* __restrict__ Wv1,
                                                const float* __restrict__ bv1){
    __shared__ float sr[OBSD];
    int b = blockIdx.x;
    for (int i = threadIdx.x; i < OBSD; i += VHD) sr[i] = obs[(size_t)b*OBSD + i];
    __syncthreads();
    int j = threadIdx.x;
    const float* W = Wv1 + j;
    float a0 = 0, a1 = 0, a2 = 0, a3 = 0;
    for (int i = 0; i < OBSD; i += 4){
        a0 += sr[i+0] * W[(size_t)(i+0)*VHD];
        a1 += sr[i+1] * W[(size_t)(i+1)*VHD];
        a2 += sr[i+2] * W[(size_t)(i+2)*VHD];
        a3 += sr[i+3] * W[(size_t)(i+3)*VHD];
    }
    g_vh[b*VHD + j] = tanhf(a0 + a1 + a2 + a3 + bv1[j]);
}

__global__ __launch_bounds__(VHD) void k_value2(const float* __restrict__ Wv2,
                                                const float* __restrict__ bv2){
    __shared__ float sr[VHD];
    int b = blockIdx.x;
    sr[threadIdx.x] = g_vh[b*VHD + threadIdx.x];
    __syncthreads();
    int j = threadIdx.x;
    const float* W = Wv2 + j;
    float a0 = 0, a1 = 0, a2 = 0, a3 = 0;
    for (int i = 0; i < VHD; i += 4){
        a0 += sr[i+0] * W[(i+0)*VHD];
        a1 += sr[i+1] * W[(i+1)*VHD];
        a2 += sr[i+2] * W[(i+2)*VHD];
        a3 += sr[i+3] * W[(i+3)*VHD];
    }
    g_vh2[b*VHD + j] = tanhf(a0 + a1 + a2 + a3 + bv2[j]);
}

__global__ void k_valueout(const float* __restrict__ Wvo, const float* __restrict__ bvo,
                           float* __restrict__ out){
    int b = threadIdx.x;
    float acc = bvo[0];
    for (int i = 0; i < VHD; i++) acc += g_vh2[b*VHD + i] * Wvo[i];
    out[BATCH*NOUTD + b] = acc;
}

// ---------------- launch ----------------
extern "C" void kernel_launch(void* const* d_in, const int* in_sizes, int n_in,
                              void* d_out, int out_size){
    const float* node_feats = (const float*)d_in[0];
    const float* obs        = (const float*)d_in[1];
    const int*   edge_src   = (const int*)  d_in[2];
    const int*   edge_dst   = (const int*)  d_in[3];
    const int*   agent      = (const int*)  d_in[4];
    const float* W_in  = (const float*)d_in[5];
    const float* Wq    = (const float*)d_in[6];
    const float* Wk    = (const float*)d_in[7];
    const float* Wv    = (const float*)d_in[8];
    const float* Wo    = (const float*)d_in[9];
    const float* ln1g  = (const float*)d_in[10];
    const float* ln1b  = (const float*)d_in[11];
    const float* W1    = (const float*)d_in[12];
    const float* b1    = (const float*)d_in[13];
    const float* W2    = (const float*)d_in[14];
    const float* b2    = (const float*)d_in[15];
    const float* ln2g  = (const float*)d_in[16];
    const float* ln2b  = (const float*)d_in[17];
    const float* Wr    = (const float*)d_in[18];
    const float* br    = (const float*)d_in[19];
    const float* Wp1   = (const float*)d_in[20];
    const float* bp1   = (const float*)d_in[21];
    const float* Wp2   = (const float*)d_in[22];
    const float* bp2   = (const float*)d_in[23];
    const float* Wlog  = (const float*)d_in[24];
    const float* blog  = (const float*)d_in[25];
    const float* Wv1   = (const float*)d_in[26];
    const float* bv1   = (const float*)d_in[27];
    const float* Wv2   = (const float*)d_in[28];
    const float* bv2   = (const float*)d_in[29];
    const float* Wvo   = (const float*)d_in[30];
    const float* bvo   = (const float*)d_in[31];
    float* out = (float*)d_out;

    cudaFuncSetAttribute((const void*)k_input, cudaFuncAttributeMaxDynamicSharedMemorySize, SM_IN);
    cudaFuncSetAttribute((const void*)k_qkv,   cudaFuncAttributeMaxDynamicSharedMemorySize, SM_QKV);
    cudaFuncSetAttribute((const void*)k_ffn1,  cudaFuncAttributeMaxDynamicSharedMemorySize, SM_FFN1);
    cudaFuncSetAttribute((const void*)k_wo_ln, cudaFuncAttributeMaxDynamicSharedMemorySize, SMEMSZ);
    cudaFuncSetAttribute((const void*)k_ffn2,  cudaFuncAttributeMaxDynamicSharedMemorySize, SMEMSZ);

    k_zero_deg<<<(TOTN + 255)/256, 256>>>();
    k_hist<<<(NEDGE + 255)/256, 256>>>(edge_dst);
    k_scan<<<1, 1024>>>();
    k_input<<<NB, NTHR, SM_IN>>>(node_feats, W_in);              // capture slot 4 (HMMA)
    k_scatter<<<(NEDGE + 255)/256, 256>>>(edge_src, edge_dst);

    for (int l = 0; l < LAYERS; l++){
        k_qkv  <<<NB, NTHR, SM_QKV>>>(Wq + l*H*H, Wk + l*H*H, Wv + l*H*H);
        k_attn <<<(TOTN*32 + 255)/256, 256>>>();
        k_wo_ln<<<NB, 128, SMEMSZ>>>(Wo + l*H*H, ln1g + l*H, ln1b + l*H);
        k_ffn1 <<<NB, NTHR, SM_FFN1>>>(W1 + l*H*2*H, b1 + l*2*H);
        k_ffn2 <<<NB, 128, SMEMSZ>>>(W2 + l*2*H*H, b2 + l*H, ln2g + l*H, ln2b + l*H);
    }

    k_gat<<<1, 128>>>(agent, Wr, br);
    k_policy1<<<BATCH, 512>>>(obs, Wp1, bp1);
    k_policy2<<<BATCH, 512>>>(Wp2, bp2);
    k_logits<<<BATCH, 32>>>(Wlog, blog, out);
    k_value1<<<BATCH, VHD>>>(obs, Wv1, bv1);
    k_value2<<<BATCH, VHD>>>(Wv2, bv2);
    k_valueout<<<1, BATCH>>>(Wvo, bvo, out);
}